// round 4
// baseline (speedup 1.0000x reference)
#include <cuda_runtime.h>
#include <math.h>

// ---------------------------------------------------------------------------
// BlockKoopmanNet fp32 baseline: tiled SGEMM + fused bias/SiLU epilogues.
// B=16384, X=64, U=16, Z=32, H=1024, A=256. All dims divide tile sizes, so
// no bounds checks anywhere.
// ---------------------------------------------------------------------------

#define KDT 0.02f
#define BATCH 16384

// Scratch (allocation-free rule: __device__ globals).
__device__ float g_bufA[BATCH * 1024];
__device__ float g_bufB[BATCH * 1024];
__device__ float g_s1[BATCH * 256];
__device__ float g_s2[BATCH * 256];
__device__ float g_z[BATCH * 32];
__device__ float g_aux[BATCH * 32];
__device__ float g_Bmat[BATCH * 512];
__device__ float g_znext[BATCH * 32];

// ---------------------------------------------------------------------------
// Generic tiled GEMM: C = act(A[M,K] @ W[K,N] + bias[N]); all row-major.
// BM x BN block tile, BK k-tile, TM x TN per-thread microtile.
// ---------------------------------------------------------------------------
template <int BM, int BN, int BK, int TM, int TN, bool ACT>
__global__ void __launch_bounds__((BM / TM) * (BN / TN))
gemm_bias_act(const float* __restrict__ A,
              const float* __restrict__ W,
              const float* __restrict__ bias,
              float* __restrict__ C,
              int M, int N, int K)
{
    constexpr int THREADS = (BM / TM) * (BN / TN);
    constexpr int KVEC = BK / 4;
    constexpr int NVEC = BN / 4;
    constexpr int A_V_PER_T = (BM * BK / 4) / THREADS;
    constexpr int W_V_PER_T = (BK * BN / 4) / THREADS;

    __shared__ __align__(16) float As[BK][BM];   // transposed: As[k][m]
    __shared__ __align__(16) float Ws[BK][BN];   // Ws[k][n]

    const int tid  = threadIdx.x;
    const int brow = blockIdx.y * BM;
    const int bcol = blockIdx.x * BN;
    const int tcol = tid % (BN / TN);
    const int trow = tid / (BN / TN);

    float acc[TM][TN];
#pragma unroll
    for (int i = 0; i < TM; i++)
#pragma unroll
        for (int j = 0; j < TN; j++) acc[i][j] = 0.0f;

    for (int k0 = 0; k0 < K; k0 += BK) {
        // Load A tile (BM x BK), float4 along K, store transposed.
#pragma unroll
        for (int v = 0; v < A_V_PER_T; v++) {
            int idx = tid + v * THREADS;
            int row = idx / KVEC;
            int kv  = idx % KVEC;
            float4 a4 = *reinterpret_cast<const float4*>(
                A + (size_t)(brow + row) * K + k0 + kv * 4);
            As[kv * 4 + 0][row] = a4.x;
            As[kv * 4 + 1][row] = a4.y;
            As[kv * 4 + 2][row] = a4.z;
            As[kv * 4 + 3][row] = a4.w;
        }
        // Load W tile (BK x BN), float4 along N.
#pragma unroll
        for (int v = 0; v < W_V_PER_T; v++) {
            int idx = tid + v * THREADS;
            int kr  = idx / NVEC;
            int nv  = idx % NVEC;
            *reinterpret_cast<float4*>(&Ws[kr][nv * 4]) =
                *reinterpret_cast<const float4*>(
                    W + (size_t)(k0 + kr) * N + bcol + nv * 4);
        }
        __syncthreads();

#pragma unroll
        for (int k = 0; k < BK; k++) {
            float ra[TM], rb[TN];
#pragma unroll
            for (int i = 0; i < TM; i += 4)
                *reinterpret_cast<float4*>(&ra[i]) =
                    *reinterpret_cast<const float4*>(&As[k][trow * TM + i]);
#pragma unroll
            for (int j = 0; j < TN; j += 4)
                *reinterpret_cast<float4*>(&rb[j]) =
                    *reinterpret_cast<const float4*>(&Ws[k][tcol * TN + j]);
#pragma unroll
            for (int i = 0; i < TM; i++)
#pragma unroll
                for (int j = 0; j < TN; j++)
                    acc[i][j] = fmaf(ra[i], rb[j], acc[i][j]);
        }
        __syncthreads();
    }

    // Epilogue: bias (+ SiLU), vectorized store.
#pragma unroll
    for (int i = 0; i < TM; i++) {
        const int r = brow + trow * TM + i;
#pragma unroll
        for (int j = 0; j < TN; j += 4) {
            float4 v;
            float* pv = &v.x;
#pragma unroll
            for (int q = 0; q < 4; q++) {
                float t = acc[i][j + q] + bias[bcol + tcol * TN + j + q];
                if (ACT) t = t / (1.0f + __expf(-t));
                pv[q] = t;
            }
            *reinterpret_cast<float4*>(
                C + (size_t)r * N + bcol + tcol * TN + j) = v;
        }
    }
}

// ---------------------------------------------------------------------------
// Combine: z_next = z + DT * (Az + Bu)
//   a=aux[2i], b=aux[2i+1]; f=exp(a DT), c=cos(b DT), s=sin(b DT)
//   Az[2i]   = f*(c*z[2i] - s*z[2i+1])
//   Az[2i+1] = f*(s*z[2i] + c*z[2i+1])
//   Bu[j] = sum_u Bmat[b, j*16+u] * u[b, u]
// One warp per batch row; lane = z index.
// ---------------------------------------------------------------------------
__global__ void combine_kernel(const float* __restrict__ z,
                               const float* __restrict__ aux,
                               const float* __restrict__ Bmat,
                               const float* __restrict__ u,
                               float* __restrict__ z_next)
{
    const int row  = blockIdx.x * (blockDim.x >> 5) + (threadIdx.x >> 5);
    const int lane = threadIdx.x & 31;
    if (row >= BATCH) return;

    const int j = lane;          // 0..31
    const int i = j >> 1;        // pair index

    const float a  = aux[row * 32 + 2 * i];
    const float bb = aux[row * 32 + 2 * i + 1];
    const float z0 = z[row * 32 + 2 * i];
    const float z1 = z[row * 32 + 2 * i + 1];

    const float f = expf(a * KDT);
    const float c = cosf(bb * KDT);
    const float s = sinf(bb * KDT);

    const float az = (j & 1) ? f * (s * z0 + c * z1)
                             : f * (c * z0 - s * z1);
    const float zj = (j & 1) ? z1 : z0;

    const float* bm = Bmat + (size_t)row * 512 + j * 16;
    const float* ur = u + (size_t)row * 16;
    float bu = 0.0f;
#pragma unroll
    for (int k = 0; k < 16; k++) bu = fmaf(bm[k], ur[k], bu);

    z_next[row * 32 + j] = zj + KDT * (az + bu);
}

// ---------------------------------------------------------------------------
extern "C" void kernel_launch(void* const* d_in, const int* in_sizes, int n_in,
                              void* d_out, int out_size)
{
    const float* x    = (const float*)d_in[0];
    const float* u    = (const float*)d_in[1];
    const float* e_w1 = (const float*)d_in[2];
    const float* e_b1 = (const float*)d_in[3];
    const float* e_w2 = (const float*)d_in[4];
    const float* e_b2 = (const float*)d_in[5];
    const float* e_w3 = (const float*)d_in[6];
    const float* e_b3 = (const float*)d_in[7];
    const float* d_w1 = (const float*)d_in[8];
    const float* d_b1 = (const float*)d_in[9];
    const float* d_w2 = (const float*)d_in[10];
    const float* d_b2 = (const float*)d_in[11];
    const float* d_w3 = (const float*)d_in[12];
    const float* d_b3 = (const float*)d_in[13];
    const float* d_w4 = (const float*)d_in[14];
    const float* d_b4 = (const float*)d_in[15];
    const float* a_w1 = (const float*)d_in[16];
    const float* a_b1 = (const float*)d_in[17];
    const float* a_w2 = (const float*)d_in[18];
    const float* a_b2 = (const float*)d_in[19];
    const float* a_w3 = (const float*)d_in[20];
    const float* a_b3 = (const float*)d_in[21];
    const float* b_w1 = (const float*)d_in[22];
    const float* b_b1 = (const float*)d_in[23];
    const float* b_w2 = (const float*)d_in[24];
    const float* b_b2 = (const float*)d_in[25];
    const float* b_w3 = (const float*)d_in[26];
    const float* b_b3 = (const float*)d_in[27];
    float* out = (float*)d_out;

    float *bufA, *bufB, *s1, *s2, *zb, *auxb, *Bm, *zn;
    cudaGetSymbolAddress((void**)&bufA, g_bufA);
    cudaGetSymbolAddress((void**)&bufB, g_bufB);
    cudaGetSymbolAddress((void**)&s1,   g_s1);
    cudaGetSymbolAddress((void**)&s2,   g_s2);
    cudaGetSymbolAddress((void**)&zb,   g_z);
    cudaGetSymbolAddress((void**)&auxb, g_aux);
    cudaGetSymbolAddress((void**)&Bm,   g_Bmat);
    cudaGetSymbolAddress((void**)&zn,   g_znext);

    const int B  = BATCH;
    const int GY = B / 128;   // 128 row-blocks

    // ---- encoder: x -> h1 -> h2 -> z ----
    gemm_bias_act<128,128,16,8,8,true ><<<dim3(1024/128, GY), 256>>>(x,    e_w1, e_b1, bufA, B, 1024,   64);
    gemm_bias_act<128,128,16,8,8,true ><<<dim3(1024/128, GY), 256>>>(bufA, e_w2, e_b2, bufB, B, 1024, 1024);
    gemm_bias_act<128, 32,16,8,4,false><<<dim3(      1, GY), 128>>>(bufB, e_w3, e_b3, zb,   B,   32, 1024);

    // ---- aux net: x -> a1 -> a2 -> aux ----
    gemm_bias_act<128, 64,16,8,4,true ><<<dim3( 256/64, GY), 256>>>(x,  a_w1, a_b1, s1,   B, 256,  64);
    gemm_bias_act<128, 64,16,8,4,true ><<<dim3( 256/64, GY), 256>>>(s1, a_w2, a_b2, s2,   B, 256, 256);
    gemm_bias_act<128, 32,16,8,4,false><<<dim3(      1, GY), 128>>>(s2, a_w3, a_b3, auxb, B,  32, 256);

    // ---- B net: x -> b1 -> b2 -> Bmat ----
    gemm_bias_act<128, 64,16,8,4,true ><<<dim3( 256/64, GY), 256>>>(x,  b_w1, b_b1, s1, B, 256,  64);
    gemm_bias_act<128, 64,16,8,4,true ><<<dim3( 256/64, GY), 256>>>(s1, b_w2, b_b2, s2, B, 256, 256);
    gemm_bias_act<128, 64,16,8,4,false><<<dim3( 512/64, GY), 256>>>(s2, b_w3, b_b3, Bm, B, 512, 256);

    // ---- dynamics combine ----
    combine_kernel<<<B / 8, 256>>>(zb, auxb, Bm, u, zn);

    // ---- decoder: z_next -> h -> h -> h -> out ----
    gemm_bias_act<128,128,16,8,8,true ><<<dim3(1024/128, GY), 256>>>(zn,   d_w1, d_b1, bufA, B, 1024,   32);
    gemm_bias_act<128,128,16,8,8,true ><<<dim3(1024/128, GY), 256>>>(bufA, d_w2, d_b2, bufB, B, 1024, 1024);
    gemm_bias_act<128,128,16,8,8,true ><<<dim3(1024/128, GY), 256>>>(bufB, d_w3, d_b3, bufA, B, 1024, 1024);
    gemm_bias_act<128, 64,16,8,4,false><<<dim3(  64/64, GY), 256>>>(bufA, d_w4, d_b4, out,  B,   64, 1024);
}

// round 6
// speedup vs baseline: 2.5271x; 2.5271x over previous
#include <cuda_runtime.h>
#include <math.h>
#include <stdint.h>

// ---------------------------------------------------------------------------
// BlockKoopmanNet — tf32 tensor-core GEMMs (mma.sync.m16n8k8) + fused
// bias/SiLU epilogues. B=16384, X=64, U=16, Z=32, H=1024, A=256.
// ---------------------------------------------------------------------------

#define KDT 0.02f
#define BATCH 16384

// Scratch (allocation-free rule: __device__ globals).
__device__ float g_bufA[BATCH * 1024];
__device__ float g_bufB[BATCH * 1024];
__device__ float g_s1[BATCH * 256];
__device__ float g_s2[BATCH * 256];
__device__ float g_z[BATCH * 32];
__device__ float g_aux[BATCH * 32];
__device__ float g_Bmat[BATCH * 512];
__device__ float g_znext[BATCH * 32];

__device__ __forceinline__ uint32_t f2tf(float x) {
    uint32_t r;
    asm("cvt.rna.tf32.f32 %0, %1;" : "=r"(r) : "f"(x));
    return r;
}

__device__ __forceinline__ void mma8(float* d, const uint32_t* a, const uint32_t* b) {
    asm volatile(
        "mma.sync.aligned.m16n8k8.row.col.f32.tf32.tf32.f32 "
        "{%0,%1,%2,%3}, {%4,%5,%6,%7}, {%8,%9}, {%0,%1,%2,%3};"
        : "+f"(d[0]), "+f"(d[1]), "+f"(d[2]), "+f"(d[3])
        : "r"(a[0]), "r"(a[1]), "r"(a[2]), "r"(a[3]), "r"(b[0]), "r"(b[1]));
}

// ---------------------------------------------------------------------------
// C = act(A[M,K] @ W[K,N] + bias). Row-major everywhere.
// BM=128, BK=16 fixed. 8 warps (256 threads), warp tile WM x WN.
// Smem natural layout, padded strides conflict-free for the m16n8k8 gather
// (A stride 20, W stride BN+8). tf32 cvt.rna applied at staging-store time.
// Register-prefetch double buffer; ONE __syncthreads per k-tile (the post-
// STS barrier of iter t already orders all reads of stage s^1 from iter t-1
// against the STS of iter t+1).
// ---------------------------------------------------------------------------
template <int BN, int WM, int WN, bool ACT>
__global__ void __launch_bounds__(256, 2)
gemm_tf32(const float* __restrict__ A, const float* __restrict__ W,
          const float* __restrict__ bias, float* __restrict__ C,
          int M, int N, int K)
{
    constexpr int BM = 128, BK = 16;
    constexpr int MT = WM / 16;          // m16 tiles per warp
    constexpr int NT = WN / 8;           // n8 tiles per warp
    constexpr int WARPS_N = BN / WN;
    constexpr int ASTR = BK + 4;         // 20 words: conflict-free frag LDS
    constexpr int WSTR = BN + 8;         // bank = 8*tg + g: bijective mod 32
    constexpr int WTOT = BK * BN / 4;    // float4 slots in W tile
    constexpr int WV   = (WTOT + 255) / 256;
    constexpr bool WGUARD = (WTOT % 256) != 0;

    __shared__ uint32_t As[2][BM * ASTR];
    __shared__ uint32_t Ws[2][BK * WSTR];

    const int tid  = threadIdx.x;
    const int lane = tid & 31;
    const int wid  = tid >> 5;
    const int wm   = wid / WARPS_N;
    const int wn   = wid % WARPS_N;
    const int brow = blockIdx.y * BM;
    const int bcol = blockIdx.x * BN;
    const int g    = lane >> 2;          // group id (0..7)
    const int tg   = lane & 3;           // thread-in-group

    float acc[MT][NT][4];
#pragma unroll
    for (int m = 0; m < MT; m++)
#pragma unroll
        for (int n = 0; n < NT; n++)
#pragma unroll
            for (int q = 0; q < 4; q++) acc[m][n][q] = 0.0f;

    float4 ra[2];
    float4 rw[WV];

    const int nk = K / BK;

    // ---- prefetch tile 0 into registers ----
    {
#pragma unroll
        for (int v = 0; v < 2; v++) {
            int idx = tid + v * 256;
            int row = idx >> 2, c4 = (idx & 3) * 4;
            ra[v] = *reinterpret_cast<const float4*>(
                A + (size_t)(brow + row) * K + c4);
        }
#pragma unroll
        for (int v = 0; v < WV; v++) {
            int idx = tid + v * 256;
            if (!WGUARD || idx < WTOT) {
                int kk = idx / (BN / 4), c4 = (idx % (BN / 4)) * 4;
                rw[v] = *reinterpret_cast<const float4*>(
                    W + (size_t)kk * N + bcol + c4);
            }
        }
    }

    for (int t = 0; t < nk; t++) {
        const int s = t & 1;

        // ---- store staged registers (tf32-converted) ----
#pragma unroll
        for (int v = 0; v < 2; v++) {
            int idx = tid + v * 256;
            int row = idx >> 2, c4 = (idx & 3) * 4;
            uint4 p = {f2tf(ra[v].x), f2tf(ra[v].y), f2tf(ra[v].z), f2tf(ra[v].w)};
            *reinterpret_cast<uint4*>(&As[s][row * ASTR + c4]) = p;
        }
#pragma unroll
        for (int v = 0; v < WV; v++) {
            int idx = tid + v * 256;
            if (!WGUARD || idx < WTOT) {
                int kk = idx / (BN / 4), c4 = (idx % (BN / 4)) * 4;
                uint4 p = {f2tf(rw[v].x), f2tf(rw[v].y), f2tf(rw[v].z), f2tf(rw[v].w)};
                *reinterpret_cast<uint4*>(&Ws[s][kk * WSTR + c4]) = p;
            }
        }
        __syncthreads();

        // ---- prefetch next tile (global -> regs; overlaps compute) ----
        if (t + 1 < nk) {
            const int k0 = (t + 1) * BK;
#pragma unroll
            for (int v = 0; v < 2; v++) {
                int idx = tid + v * 256;
                int row = idx >> 2, c4 = (idx & 3) * 4;
                ra[v] = *reinterpret_cast<const float4*>(
                    A + (size_t)(brow + row) * K + k0 + c4);
            }
#pragma unroll
            for (int v = 0; v < WV; v++) {
                int idx = tid + v * 256;
                if (!WGUARD || idx < WTOT) {
                    int kk = idx / (BN / 4), c4 = (idx % (BN / 4)) * 4;
                    rw[v] = *reinterpret_cast<const float4*>(
                        W + (size_t)(k0 + kk) * N + bcol + c4);
                }
            }
        }

        // ---- compute: 2 k-steps of 8 ----
#pragma unroll
        for (int ks = 0; ks < BK / 8; ks++) {
            uint32_t af[MT][4];
#pragma unroll
            for (int m = 0; m < MT; m++) {
                const int r0  = wm * WM + m * 16;
                const int col = ks * 8 + tg;
                af[m][0] = As[s][(r0 + g)     * ASTR + col];
                af[m][1] = As[s][(r0 + 8 + g) * ASTR + col];
                af[m][2] = As[s][(r0 + g)     * ASTR + col + 4];
                af[m][3] = As[s][(r0 + 8 + g) * ASTR + col + 4];
            }
            uint32_t bf[NT][2];
#pragma unroll
            for (int n = 0; n < NT; n++) {
                const int cb = wn * WN + n * 8 + g;
                bf[n][0] = Ws[s][(ks * 8 + tg)     * WSTR + cb];
                bf[n][1] = Ws[s][(ks * 8 + 4 + tg) * WSTR + cb];
            }
#pragma unroll
            for (int m = 0; m < MT; m++)
#pragma unroll
                for (int n = 0; n < NT; n++)
                    mma8(acc[m][n], af[m], bf[n]);
        }
        // single-barrier double buffer: see header comment.
    }

    // ---- epilogue: bias (+ SiLU), float2 stores ----
#pragma unroll
    for (int m = 0; m < MT; m++) {
#pragma unroll
        for (int n = 0; n < NT; n++) {
            const int r0 = brow + wm * WM + m * 16 + g;
            const int cc = bcol + wn * WN + n * 8 + tg * 2;
            const float b0 = bias[cc], b1 = bias[cc + 1];
            float v0 = acc[m][n][0] + b0;
            float v1 = acc[m][n][1] + b1;
            float v2 = acc[m][n][2] + b0;
            float v3 = acc[m][n][3] + b1;
            if (ACT) {
                v0 = v0 / (1.0f + __expf(-v0));
                v1 = v1 / (1.0f + __expf(-v1));
                v2 = v2 / (1.0f + __expf(-v2));
                v3 = v3 / (1.0f + __expf(-v3));
            }
            float2 lo = {v0, v1}, hi = {v2, v3};
            *reinterpret_cast<float2*>(C + (size_t)r0 * N + cc) = lo;
            *reinterpret_cast<float2*>(C + (size_t)(r0 + 8) * N + cc) = hi;
        }
    }
}

// ---------------------------------------------------------------------------
// Combine: z_next = z + DT * (Az + Bu). One warp per batch row.
// ---------------------------------------------------------------------------
__global__ void combine_kernel(const float* __restrict__ z,
                               const float* __restrict__ aux,
                               const float* __restrict__ Bmat,
                               const float* __restrict__ u,
                               float* __restrict__ z_next)
{
    const int row  = blockIdx.x * (blockDim.x >> 5) + (threadIdx.x >> 5);
    const int lane = threadIdx.x & 31;
    if (row >= BATCH) return;

    const int j = lane;
    const int i = j >> 1;

    const float a  = aux[row * 32 + 2 * i];
    const float bb = aux[row * 32 + 2 * i + 1];
    const float z0 = z[row * 32 + 2 * i];
    const float z1 = z[row * 32 + 2 * i + 1];

    const float f = expf(a * KDT);
    const float c = cosf(bb * KDT);
    const float s = sinf(bb * KDT);

    const float az = (j & 1) ? f * (s * z0 + c * z1)
                             : f * (c * z0 - s * z1);
    const float zj = (j & 1) ? z1 : z0;

    const float* bm = Bmat + (size_t)row * 512 + j * 16;
    const float* ur = u + (size_t)row * 16;
    float bu = 0.0f;
#pragma unroll
    for (int k = 0; k < 16; k++) bu = fmaf(bm[k], ur[k], bu);

    z_next[row * 32 + j] = zj + KDT * (az + bu);
}

// ---------------------------------------------------------------------------
extern "C" void kernel_launch(void* const* d_in, const int* in_sizes, int n_in,
                              void* d_out, int out_size)
{
    const float* x    = (const float*)d_in[0];
    const float* u    = (const float*)d_in[1];
    const float* e_w1 = (const float*)d_in[2];
    const float* e_b1 = (const float*)d_in[3];
    const float* e_w2 = (const float*)d_in[4];
    const float* e_b2 = (const float*)d_in[5];
    const float* e_w3 = (const float*)d_in[6];
    const float* e_b3 = (const float*)d_in[7];
    const float* d_w1 = (const float*)d_in[8];
    const float* d_b1 = (const float*)d_in[9];
    const float* d_w2 = (const float*)d_in[10];
    const float* d_b2 = (const float*)d_in[11];
    const float* d_w3 = (const float*)d_in[12];
    const float* d_b3 = (const float*)d_in[13];
    const float* d_w4 = (const float*)d_in[14];
    const float* d_b4 = (const float*)d_in[15];
    const float* a_w1 = (const float*)d_in[16];
    const float* a_b1 = (const float*)d_in[17];
    const float* a_w2 = (const float*)d_in[18];
    const float* a_b2 = (const float*)d_in[19];
    const float* a_w3 = (const float*)d_in[20];
    const float* a_b3 = (const float*)d_in[21];
    const float* b_w1 = (const float*)d_in[22];
    const float* b_b1 = (const float*)d_in[23];
    const float* b_w2 = (const float*)d_in[24];
    const float* b_b2 = (const float*)d_in[25];
    const float* b_w3 = (const float*)d_in[26];
    const float* b_b3 = (const float*)d_in[27];
    float* out = (float*)d_out;

    float *bufA, *bufB, *s1, *s2, *zb, *auxb, *Bm, *zn;
    cudaGetSymbolAddress((void**)&bufA, g_bufA);
    cudaGetSymbolAddress((void**)&bufB, g_bufB);
    cudaGetSymbolAddress((void**)&s1,   g_s1);
    cudaGetSymbolAddress((void**)&s2,   g_s2);
    cudaGetSymbolAddress((void**)&zb,   g_z);
    cudaGetSymbolAddress((void**)&auxb, g_aux);
    cudaGetSymbolAddress((void**)&Bm,   g_Bmat);
    cudaGetSymbolAddress((void**)&zn,   g_znext);

    const int B  = BATCH;
    const int GY = B / 128;
    const dim3 blk(256);

    // ---- encoder: x -> h1 -> h2 -> z ----
    gemm_tf32<128,64,32,true ><<<dim3(1024/128, GY), blk>>>(x,    e_w1, e_b1, bufA, B, 1024,   64);
    gemm_tf32<128,64,32,true ><<<dim3(1024/128, GY), blk>>>(bufA, e_w2, e_b2, bufB, B, 1024, 1024);
    gemm_tf32< 32,16,32,false><<<dim3(       1, GY), blk>>>(bufB, e_w3, e_b3, zb,   B,   32, 1024);

    // ---- aux net ----
    gemm_tf32<128,64,32,true ><<<dim3( 256/128, GY), blk>>>(x,  a_w1, a_b1, s1,   B, 256,  64);
    gemm_tf32<128,64,32,true ><<<dim3( 256/128, GY), blk>>>(s1, a_w2, a_b2, s2,   B, 256, 256);
    gemm_tf32< 32,16,32,false><<<dim3(       1, GY), blk>>>(s2, a_w3, a_b3, auxb, B,  32, 256);

    // ---- B net ----
    gemm_tf32<128,64,32,true ><<<dim3( 256/128, GY), blk>>>(x,  b_w1, b_b1, s1, B, 256,  64);
    gemm_tf32<128,64,32,true ><<<dim3( 256/128, GY), blk>>>(s1, b_w2, b_b2, s2, B, 256, 256);
    gemm_tf32<128,64,32,false><<<dim3( 512/128, GY), blk>>>(s2, b_w3, b_b3, Bm, B, 512, 256);

    // ---- dynamics combine ----
    combine_kernel<<<B / 8, 256>>>(zb, auxb, Bm, u, zn);

    // ---- decoder ----
    gemm_tf32<128,64,32,true ><<<dim3(1024/128, GY), blk>>>(zn,   d_w1, d_b1, bufA, B, 1024,   32);
    gemm_tf32<128,64,32,true ><<<dim3(1024/128, GY), blk>>>(bufA, d_w2, d_b2, bufB, B, 1024, 1024);
    gemm_tf32<128,64,32,true ><<<dim3(1024/128, GY), blk>>>(bufB, d_w3, d_b3, bufA, B, 1024, 1024);
    gemm_tf32< 64,32,32,false><<<dim3(   64/64, GY), blk>>>(bufA, d_w4, d_b4, out,  B,   64, 1024);
}

// round 8
// speedup vs baseline: 2.7018x; 1.0691x over previous
#include <cuda_runtime.h>
#include <math.h>
#include <stdint.h>

// ---------------------------------------------------------------------------
// BlockKoopmanNet — tf32 tensor-core GEMMs (mma.sync.m16n8k8) with cp.async
// 3-stage pipeline. All GEMM operands are pre-rounded to tf32 values, so the
// mainloop feeds raw fp32 bits to the MMA (bit-identical to cvt.rna staging).
// B=16384, X=64, U=16, Z=32, H=1024, A=256.
// ---------------------------------------------------------------------------

#define KDT 0.02f
#define BATCH 16384

// Scratch (allocation-free rule: __device__ globals).
__device__ float g_bufA[BATCH * 1024];
__device__ float g_bufB[BATCH * 1024];
__device__ float g_s1[BATCH * 256];
__device__ float g_s2[BATCH * 256];
__device__ float g_z[BATCH * 32];
__device__ float g_aux[BATCH * 32];
__device__ float g_Bmat[BATCH * 512];
__device__ float g_znext[BATCH * 32];
__device__ float g_xr[BATCH * 64];          // tf32-rounded x
__device__ float g_wr[3645440];             // tf32-rounded weights (all nets)

__device__ __forceinline__ float tfround(float x) {
    uint32_t r;
    asm("cvt.rna.tf32.f32 %0, %1;" : "=r"(r) : "f"(x));
    return __uint_as_float(r);
}

__device__ __forceinline__ void mma8(float* d, const uint32_t* a, const uint32_t* b) {
    asm volatile(
        "mma.sync.aligned.m16n8k8.row.col.f32.tf32.tf32.f32 "
        "{%0,%1,%2,%3}, {%4,%5,%6,%7}, {%8,%9}, {%0,%1,%2,%3};"
        : "+f"(d[0]), "+f"(d[1]), "+f"(d[2]), "+f"(d[3])
        : "r"(a[0]), "r"(a[1]), "r"(a[2]), "r"(a[3]), "r"(b[0]), "r"(b[1]));
}

__device__ __forceinline__ void cpa8(uint32_t dst, const float* src) {
    asm volatile("cp.async.ca.shared.global [%0], [%1], 8;" :: "r"(dst), "l"(src));
}
__device__ __forceinline__ void cpa16(uint32_t dst, const float* src) {
    asm volatile("cp.async.cg.shared.global [%0], [%1], 16;" :: "r"(dst), "l"(src));
}
__device__ __forceinline__ void cpa_commit() {
    asm volatile("cp.async.commit_group;");
}
__device__ __forceinline__ void cpa_wait1() {
    asm volatile("cp.async.wait_group 1;");
}

// ---------------------------------------------------------------------------
// Pre-round: dst[i] = tf32_rna(src[i]). n is a multiple of 4.
// ---------------------------------------------------------------------------
__global__ void round_copy(const float4* __restrict__ src,
                           float4* __restrict__ dst, int n4)
{
    int i = blockIdx.x * blockDim.x + threadIdx.x;
    const int stride = gridDim.x * blockDim.x;
    for (; i < n4; i += stride) {
        float4 v = src[i];
        dst[i] = make_float4(tfround(v.x), tfround(v.y), tfround(v.z), tfround(v.w));
    }
}

// ---------------------------------------------------------------------------
// C = act(A[M,K] @ W[K,N] + bias). Row-major. BM=128, BK=16, 3-stage cp.async.
// 8 warps (256 threads), warp tile WM x WN. A smem stride 20 words (8B-aligned
// rows, conflict-free frag gather: banks 20g+tg all distinct); W stride BN+8
// (16B-aligned rows, banks 8tg+g all distinct). ACT layers apply SiLU and
// tf32-round their output (it feeds another GEMM).
// ---------------------------------------------------------------------------
template <int BN, int WM, int WN, bool ACT>
__global__ void __launch_bounds__(256, 2)
gemm_tf32(const float* __restrict__ A, const float* __restrict__ W,
          const float* __restrict__ bias, float* __restrict__ C,
          int M, int N, int K)
{
    constexpr int BM = 128, BK = 16, S = 3;
    constexpr int MT = WM / 16;
    constexpr int NT = WN / 8;
    constexpr int WARPS_N = BN / WN;
    constexpr int ASTR = 20;              // words per A row
    constexpr int WSTR = BN + 8;          // words per W row
    constexpr int AWORDS = BM * ASTR;
    constexpr int WWORDS = BK * WSTR;
    constexpr int WTOT = BK * BN / 4;     // float4 chunks in W tile
    constexpr int WV = (WTOT + 255) / 256;
    constexpr bool WGUARD = (WTOT % 256) != 0;

    __shared__ uint32_t As[S][AWORDS];
    __shared__ uint32_t Ws[S][WWORDS];

    const int tid  = threadIdx.x;
    const int lane = tid & 31;
    const int wid  = tid >> 5;
    const int wm   = wid / WARPS_N;
    const int wn   = wid % WARPS_N;
    const int brow = blockIdx.y * BM;
    const int bcol = blockIdx.x * BN;
    const int g    = lane >> 2;
    const int tg   = lane & 3;

    const uint32_t a_sm = (uint32_t)__cvta_generic_to_shared(&As[0][0]);
    const uint32_t w_sm = (uint32_t)__cvta_generic_to_shared(&Ws[0][0]);

    const int nk = K / BK;

    float acc[MT][NT][4];
#pragma unroll
    for (int m = 0; m < MT; m++)
#pragma unroll
        for (int n = 0; n < NT; n++)
#pragma unroll
            for (int q = 0; q < 4; q++) acc[m][n][q] = 0.0f;

    // ---- async tile issue: A as 8B chunks, W as 16B chunks ----
    auto issue_tile = [&](int t) {
        if (t < nk) {
            const int s  = (t % S);
            const int k0 = t * BK;
            const uint32_t ab = a_sm + (uint32_t)s * AWORDS * 4;
            const uint32_t wb = w_sm + (uint32_t)s * WWORDS * 4;
#pragma unroll
            for (int v = 0; v < 4; v++) {               // 1024 chunks / 256
                int idx = tid + v * 256;
                int row = idx >> 3, ch = idx & 7;       // 8 chunks per row
                cpa8(ab + (uint32_t)(row * ASTR + ch * 2) * 4,
                     A + (size_t)(brow + row) * K + k0 + ch * 2);
            }
#pragma unroll
            for (int v = 0; v < WV; v++) {
                int idx = tid + v * 256;
                if (!WGUARD || idx < WTOT) {
                    int kk = idx / (BN / 4), c4 = (idx % (BN / 4)) * 4;
                    cpa16(wb + (uint32_t)(kk * WSTR + c4) * 4,
                          W + (size_t)(k0 + kk) * N + bcol + c4);
                }
            }
        }
        cpa_commit();
    };

    issue_tile(0);
    issue_tile(1);

    for (int t = 0; t < nk; t++) {
        const int s = t % S;
        cpa_wait1();           // tile t resident
        __syncthreads();       // visible to all; prior readers of stage done
        issue_tile(t + 2);     // into stage (t+2)%S — not read until t+2

#pragma unroll
        for (int ks = 0; ks < BK / 8; ks++) {
            uint32_t af[MT][4];
#pragma unroll
            for (int m = 0; m < MT; m++) {
                const int r0  = wm * WM + m * 16;
                const int col = ks * 8 + tg;
                af[m][0] = As[s][(r0 + g)     * ASTR + col];
                af[m][1] = As[s][(r0 + 8 + g) * ASTR + col];
                af[m][2] = As[s][(r0 + g)     * ASTR + col + 4];
                af[m][3] = As[s][(r0 + 8 + g) * ASTR + col + 4];
            }
            uint32_t bf[NT][2];
#pragma unroll
            for (int n = 0; n < NT; n++) {
                const int cb = wn * WN + n * 8 + g;
                bf[n][0] = Ws[s][(ks * 8 + tg)     * WSTR + cb];
                bf[n][1] = Ws[s][(ks * 8 + 4 + tg) * WSTR + cb];
            }
#pragma unroll
            for (int m = 0; m < MT; m++)
#pragma unroll
                for (int n = 0; n < NT; n++)
                    mma8(acc[m][n], af[m], bf[n]);
        }
    }

    // ---- epilogue: bias (+ SiLU + tf32 round), float2 stores ----
#pragma unroll
    for (int m = 0; m < MT; m++) {
#pragma unroll
        for (int n = 0; n < NT; n++) {
            const int r0 = brow + wm * WM + m * 16 + g;
            const int cc = bcol + wn * WN + n * 8 + tg * 2;
            const float b0 = bias[cc], b1 = bias[cc + 1];
            float v0 = acc[m][n][0] + b0;
            float v1 = acc[m][n][1] + b1;
            float v2 = acc[m][n][2] + b0;
            float v3 = acc[m][n][3] + b1;
            if (ACT) {
                v0 = tfround(v0 / (1.0f + __expf(-v0)));
                v1 = tfround(v1 / (1.0f + __expf(-v1)));
                v2 = tfround(v2 / (1.0f + __expf(-v2)));
                v3 = tfround(v3 / (1.0f + __expf(-v3)));
            }
            float2 lo = {v0, v1}, hi = {v2, v3};
            *reinterpret_cast<float2*>(C + (size_t)r0 * N + cc) = lo;
            *reinterpret_cast<float2*>(C + (size_t)(r0 + 8) * N + cc) = hi;
        }
    }
}

// ---------------------------------------------------------------------------
// Combine: z_next = tf32_round(z + DT*(Az + Bu)) — feeds the decoder GEMM.
// ---------------------------------------------------------------------------
__global__ void combine_kernel(const float* __restrict__ z,
                               const float* __restrict__ aux,
                               const float* __restrict__ Bmat,
                               const float* __restrict__ u,
                               float* __restrict__ z_next)
{
    const int row  = blockIdx.x * (blockDim.x >> 5) + (threadIdx.x >> 5);
    const int lane = threadIdx.x & 31;
    if (row >= BATCH) return;

    const int j = lane;
    const int i = j >> 1;

    const float a  = aux[row * 32 + 2 * i];
    const float bb = aux[row * 32 + 2 * i + 1];
    const float z0 = z[row * 32 + 2 * i];
    const float z1 = z[row * 32 + 2 * i + 1];

    const float f = expf(a * KDT);
    const float c = cosf(bb * KDT);
    const float s = sinf(bb * KDT);

    const float az = (j & 1) ? f * (s * z0 + c * z1)
                             : f * (c * z0 - s * z1);
    const float zj = (j & 1) ? z1 : z0;

    const float* bm = Bmat + (size_t)row * 512 + j * 16;
    const float* ur = u + (size_t)row * 16;
    float bu = 0.0f;
#pragma unroll
    for (int k = 0; k < 16; k++) bu = fmaf(bm[k], ur[k], bu);

    z_next[row * 32 + j] = tfround(zj + KDT * (az + bu));
}

// ---------------------------------------------------------------------------
extern "C" void kernel_launch(void* const* d_in, const int* in_sizes, int n_in,
                              void* d_out, int out_size)
{
    const float* x    = (const float*)d_in[0];
    const float* u    = (const float*)d_in[1];
    const float* e_w1 = (const float*)d_in[2];
    const float* e_b1 = (const float*)d_in[3];
    const float* e_w2 = (const float*)d_in[4];
    const float* e_b2 = (const float*)d_in[5];
    const float* e_w3 = (const float*)d_in[6];
    const float* e_b3 = (const float*)d_in[7];
    const float* d_w1 = (const float*)d_in[8];
    const float* d_b1 = (const float*)d_in[9];
    const float* d_w2 = (const float*)d_in[10];
    const float* d_b2 = (const float*)d_in[11];
    const float* d_w3 = (const float*)d_in[12];
    const float* d_b3 = (const float*)d_in[13];
    const float* d_w4 = (const float*)d_in[14];
    const float* d_b4 = (const float*)d_in[15];
    const float* a_w1 = (const float*)d_in[16];
    const float* a_b1 = (const float*)d_in[17];
    const float* a_w2 = (const float*)d_in[18];
    const float* a_b2 = (const float*)d_in[19];
    const float* a_w3 = (const float*)d_in[20];
    const float* a_b3 = (const float*)d_in[21];
    const float* b_w1 = (const float*)d_in[22];
    const float* b_b1 = (const float*)d_in[23];
    const float* b_w2 = (const float*)d_in[24];
    const float* b_b2 = (const float*)d_in[25];
    const float* b_w3 = (const float*)d_in[26];
    const float* b_b3 = (const float*)d_in[27];
    float* out = (float*)d_out;

    float *bufA, *bufB, *s1, *s2, *zb, *auxb, *Bm, *zn, *xr, *wr;
    cudaGetSymbolAddress((void**)&bufA, g_bufA);
    cudaGetSymbolAddress((void**)&bufB, g_bufB);
    cudaGetSymbolAddress((void**)&s1,   g_s1);
    cudaGetSymbolAddress((void**)&s2,   g_s2);
    cudaGetSymbolAddress((void**)&zb,   g_z);
    cudaGetSymbolAddress((void**)&auxb, g_aux);
    cudaGetSymbolAddress((void**)&Bm,   g_Bmat);
    cudaGetSymbolAddress((void**)&zn,   g_znext);
    cudaGetSymbolAddress((void**)&xr,   g_xr);
    cudaGetSymbolAddress((void**)&wr,   g_wr);

    // tf32-rounded weight copies (offsets in floats into g_wr)
    float* e_w1r = wr + 0;
    float* e_w2r = wr + 65536;
    float* e_w3r = wr + 1114112;
    float* d_w1r = wr + 1146880;
    float* d_w2r = wr + 1179648;
    float* d_w3r = wr + 2228224;
    float* d_w4r = wr + 3276800;
    float* a_w1r = wr + 3342336;
    float* a_w2r = wr + 3358720;
    float* a_w3r = wr + 3424256;
    float* b_w1r = wr + 3432448;
    float* b_w2r = wr + 3448832;
    float* b_w3r = wr + 3514368;

    auto rcopy = [](const float* s, float* d, int n) {
        int n4 = n / 4;
        int blocks = (n4 + 255) / 256;
        if (blocks > 2048) blocks = 2048;
        round_copy<<<blocks, 256>>>((const float4*)s, (float4*)d, n4);
    };

    rcopy(x,    xr,    BATCH * 64);
    rcopy(e_w1, e_w1r, 64 * 1024);
    rcopy(e_w2, e_w2r, 1024 * 1024);
    rcopy(e_w3, e_w3r, 1024 * 32);
    rcopy(d_w1, d_w1r, 32 * 1024);
    rcopy(d_w2, d_w2r, 1024 * 1024);
    rcopy(d_w3, d_w3r, 1024 * 1024);
    rcopy(d_w4, d_w4r, 1024 * 64);
    rcopy(a_w1, a_w1r, 64 * 256);
    rcopy(a_w2, a_w2r, 256 * 256);
    rcopy(a_w3, a_w3r, 256 * 32);
    rcopy(b_w1, b_w1r, 64 * 256);
    rcopy(b_w2, b_w2r, 256 * 256);
    rcopy(b_w3, b_w3r, 256 * 512);

    const int B  = BATCH;
    const int GY = B / 128;
    const dim3 blk(256);

    // ---- encoder: x -> h1 -> h2 -> z ----
    gemm_tf32<128,64,32,true ><<<dim3(1024/128, GY), blk>>>(xr,   e_w1r, e_b1, bufA, B, 1024,   64);
    gemm_tf32<128,64,32,true ><<<dim3(1024/128, GY), blk>>>(bufA, e_w2r, e_b2, bufB, B, 1024, 1024);
    gemm_tf32< 32,16,32,false><<<dim3(       1, GY), blk>>>(bufB, e_w3r, e_b3, zb,   B,   32, 1024);

    // ---- aux net ----
    gemm_tf32<128,64,32,true ><<<dim3( 256/128, GY), blk>>>(xr, a_w1r, a_b1, s1,   B, 256,  64);
    gemm_tf32<128,64,32,true ><<<dim3( 256/128, GY), blk>>>(s1, a_w2r, a_b2, s2,   B, 256, 256);
    gemm_tf32< 32,16,32,false><<<dim3(       1, GY), blk>>>(s2, a_w3r, a_b3, auxb, B,  32, 256);

    // ---- B net ----
    gemm_tf32<128,64,32,true ><<<dim3( 256/128, GY), blk>>>(xr, b_w1r, b_b1, s1, B, 256,  64);
    gemm_tf32<128,64,32,true ><<<dim3( 256/128, GY), blk>>>(s1, b_w2r, b_b2, s2, B, 256, 256);
    gemm_tf32<128,64,32,false><<<dim3( 512/128, GY), blk>>>(s2, b_w3r, b_b3, Bm, B, 512, 256);

    // ---- dynamics combine (rounds z_next for decoder) ----
    combine_kernel<<<B / 8, 256>>>(zb, auxb, Bm, u, zn);

    // ---- decoder ----
    gemm_tf32<128,64,32,true ><<<dim3(1024/128, GY), blk>>>(zn,   d_w1r, d_b1, bufA, B, 1024,   32);
    gemm_tf32<128,64,32,true ><<<dim3(1024/128, GY), blk>>>(bufA, d_w2r, d_b2, bufB, B, 1024, 1024);
    gemm_tf32<128,64,32,true ><<<dim3(1024/128, GY), blk>>>(bufB, d_w3r, d_b3, bufA, B, 1024, 1024);
    gemm_tf32< 64,32,32,false><<<dim3(   64/64, GY), blk>>>(bufA, d_w4r, d_b4, out,  B,   64, 1024);
}

// round 12
// speedup vs baseline: 3.0651x; 1.1345x over previous
#include <cuda_runtime.h>
#include <math.h>
#include <stdint.h>

// ---------------------------------------------------------------------------
// BlockKoopmanNet — tf32 tensor-core GEMMs (mma.sync.m16n8k8), cp.async
// 4-stage pipeline. All GEMM operands pre-rounded to tf32 values in ONE
// fused prep launch; mainloop feeds raw fp32 bits to the MMA.
// B=16384, X=64, U=16, Z=32, H=1024, A=256.
// ---------------------------------------------------------------------------

#define KDT 0.02f
#define BATCH 16384

// Scratch (allocation-free rule: __device__ globals).
__device__ float g_bufA[BATCH * 1024];
__device__ float g_bufB[BATCH * 1024];
__device__ float g_s1[BATCH * 256];
__device__ float g_s2[BATCH * 256];
__device__ float g_z[BATCH * 32];
__device__ float g_aux[BATCH * 32];
__device__ float g_Bmat[BATCH * 512];
__device__ float g_znext[BATCH * 32];
__device__ float g_xr[BATCH * 64];          // tf32-rounded x
__device__ float g_wr[3645440];             // tf32-rounded weights (all nets)

__device__ __forceinline__ float tfround(float x) {
    uint32_t r;
    asm("cvt.rna.tf32.f32 %0, %1;" : "=r"(r) : "f"(x));
    return __uint_as_float(r);
}

__device__ __forceinline__ void mma8(float* d, const uint32_t* a, const uint32_t* b) {
    asm volatile(
        "mma.sync.aligned.m16n8k8.row.col.f32.tf32.tf32.f32 "
        "{%0,%1,%2,%3}, {%4,%5,%6,%7}, {%8,%9}, {%0,%1,%2,%3};"
        : "+f"(d[0]), "+f"(d[1]), "+f"(d[2]), "+f"(d[3])
        : "r"(a[0]), "r"(a[1]), "r"(a[2]), "r"(a[3]), "r"(b[0]), "r"(b[1]));
}

__device__ __forceinline__ void cpa16(uint32_t dst, const float* src) {
    asm volatile("cp.async.cg.shared.global [%0], [%1], 16;" :: "r"(dst), "l"(src));
}
__device__ __forceinline__ void cpa_commit() {
    asm volatile("cp.async.commit_group;");
}
__device__ __forceinline__ void cpa_wait2() {
    asm volatile("cp.async.wait_group 2;");
}

// ---------------------------------------------------------------------------
// Fused pre-round: 14 segments (x + 13 weight matrices) in ONE launch.
// ---------------------------------------------------------------------------
#define NSEG 14
struct Seg { const float4* src; float4* dst; int n4; };
struct SegPack { Seg s[NSEG]; };

__global__ void round_all(SegPack p)
{
    const Seg sg = p.s[blockIdx.y];
    int i = blockIdx.x * blockDim.x + threadIdx.x;
    const int stride = gridDim.x * blockDim.x;
    for (; i < sg.n4; i += stride) {
        float4 v = sg.src[i];
        sg.dst[i] = make_float4(tfround(v.x), tfround(v.y), tfround(v.z), tfround(v.w));
    }
}

// ---------------------------------------------------------------------------
// C = act(A[M,K] @ W[K,N] + bias). Row-major. BM=128, BK=16, 8 warps.
// 4-stage cp.async pipeline, one __syncthreads per k-tile:
//   wait_group 2 (tile t resident) ; sync ; issue(t+3) ; compute(t)
// Stage (t+3)%4 was last read by compute(t-1), which finished before sync.
// A smem stride 20 words, W stride BN+8 — conflict-free fragment gathers,
// all cp.async rows 16B-aligned. Dynamic smem: S*(BM*20 + BK*(BN+8))*4.
// ---------------------------------------------------------------------------
template <int BN, int WM, int WN, bool ACT>
__global__ void __launch_bounds__(256, 2)
gemm_tf32(const float* __restrict__ A, const float* __restrict__ W,
          const float* __restrict__ bias, float* __restrict__ C,
          int M, int N, int K)
{
    constexpr int BM = 128, BK = 16, S = 4;
    constexpr int MT = WM / 16;
    constexpr int NT = WN / 8;
    constexpr int WARPS_N = BN / WN;
    constexpr int WARPS_M = 8 / WARPS_N;
    static_assert(WARPS_M * WM == BM, "warp grid must tile BM exactly");
    static_assert(WARPS_N * WN == BN, "warp grid must tile BN exactly");
    constexpr int ASTR = BK + 4;                    // 20 words
    constexpr int WSTR = BN + 8;
    constexpr int AWORDS = BM * ASTR;
    constexpr int WWORDS = BK * WSTR;
    constexpr int AV = (BM * BK / 4) / 256;         // float4 chunks/thread (A)
    constexpr int WTOT = BK * BN / 4;
    constexpr int WV = (WTOT + 255) / 256;
    constexpr bool WGUARD = (WTOT % 256) != 0;

    extern __shared__ uint32_t smem_dyn[];
    uint32_t* Asm = smem_dyn;
    uint32_t* Wsm = smem_dyn + S * AWORDS;

    const int tid  = threadIdx.x;
    const int lane = tid & 31;
    const int wid  = tid >> 5;
    const int wm   = wid / WARPS_N;
    const int wn   = wid % WARPS_N;
    const int brow = blockIdx.y * BM;
    const int bcol = blockIdx.x * BN;
    const int g    = lane >> 2;
    const int tg   = lane & 3;

    const uint32_t a_sm = (uint32_t)__cvta_generic_to_shared(Asm);
    const uint32_t w_sm = (uint32_t)__cvta_generic_to_shared(Wsm);

    const int nk = K / BK;

    float acc[MT][NT][4];
#pragma unroll
    for (int m = 0; m < MT; m++)
#pragma unroll
        for (int n = 0; n < NT; n++)
#pragma unroll
            for (int q = 0; q < 4; q++) acc[m][n][q] = 0.0f;

    auto issue_tile = [&](int t) {
        if (t < nk) {
            const int s  = t % S;
            const int k0 = t * BK;
            const uint32_t ab = a_sm + (uint32_t)s * AWORDS * 4;
            const uint32_t wb = w_sm + (uint32_t)s * WWORDS * 4;
#pragma unroll
            for (int v = 0; v < AV; v++) {
                int idx = tid + v * 256;
                int row = idx / (BK / 4), c4 = (idx % (BK / 4)) * 4;
                cpa16(ab + (uint32_t)(row * ASTR + c4) * 4,
                      A + (size_t)(brow + row) * K + k0 + c4);
            }
#pragma unroll
            for (int v = 0; v < WV; v++) {
                int idx = tid + v * 256;
                if (!WGUARD || idx < WTOT) {
                    int kk = idx / (BN / 4), c4 = (idx % (BN / 4)) * 4;
                    cpa16(wb + (uint32_t)(kk * WSTR + c4) * 4,
                          W + (size_t)(k0 + kk) * N + bcol + c4);
                }
            }
        }
        cpa_commit();
    };

    issue_tile(0);
    issue_tile(1);
    issue_tile(2);

    for (int t = 0; t < nk; t++) {
        const int s = t % S;
        cpa_wait2();
        __syncthreads();
        issue_tile(t + 3);

        const uint32_t* As = Asm + s * AWORDS;
        const uint32_t* Ws = Wsm + s * WWORDS;

#pragma unroll
        for (int ks = 0; ks < BK / 8; ks++) {
            uint32_t af[MT][4];
#pragma unroll
            for (int m = 0; m < MT; m++) {
                const int r0  = wm * WM + m * 16;
                const int col = ks * 8 + tg;
                af[m][0] = As[(r0 + g)     * ASTR + col];
                af[m][1] = As[(r0 + 8 + g) * ASTR + col];
                af[m][2] = As[(r0 + g)     * ASTR + col + 4];
                af[m][3] = As[(r0 + 8 + g) * ASTR + col + 4];
            }
            uint32_t bf[NT][2];
#pragma unroll
            for (int n = 0; n < NT; n++) {
                const int cb = wn * WN + n * 8 + g;
                bf[n][0] = Ws[(ks * 8 + tg)     * WSTR + cb];
                bf[n][1] = Ws[(ks * 8 + 4 + tg) * WSTR + cb];
            }
#pragma unroll
            for (int m = 0; m < MT; m++)
#pragma unroll
                for (int n = 0; n < NT; n++)
                    mma8(acc[m][n], af[m], bf[n]);
        }
    }

    // ---- epilogue: bias (+ SiLU + tf32 round), float2 stores ----
#pragma unroll
    for (int m = 0; m < MT; m++) {
#pragma unroll
        for (int n = 0; n < NT; n++) {
            const int r0 = brow + wm * WM + m * 16 + g;
            const int cc = bcol + wn * WN + n * 8 + tg * 2;
            const float b0 = bias[cc], b1 = bias[cc + 1];
            float v0 = acc[m][n][0] + b0;
            float v1 = acc[m][n][1] + b1;
            float v2 = acc[m][n][2] + b0;
            float v3 = acc[m][n][3] + b1;
            if (ACT) {
                v0 = tfround(v0 / (1.0f + __expf(-v0)));
                v1 = tfround(v1 / (1.0f + __expf(-v1)));
                v2 = tfround(v2 / (1.0f + __expf(-v2)));
                v3 = tfround(v3 / (1.0f + __expf(-v3)));
            }
            float2 lo = {v0, v1}, hi = {v2, v3};
            *reinterpret_cast<float2*>(C + (size_t)r0 * N + cc) = lo;
            *reinterpret_cast<float2*>(C + (size_t)(r0 + 8) * N + cc) = hi;
        }
    }
}

// ---------------------------------------------------------------------------
// Combine: z_next = tf32_round(z + DT*(Az + Bu)) — feeds the decoder GEMM.
// ---------------------------------------------------------------------------
__global__ void combine_kernel(const float* __restrict__ z,
                               const float* __restrict__ aux,
                               const float* __restrict__ Bmat,
                               const float* __restrict__ u,
                               float* __restrict__ z_next)
{
    const int row  = blockIdx.x * (blockDim.x >> 5) + (threadIdx.x >> 5);
    const int lane = threadIdx.x & 31;
    if (row >= BATCH) return;

    const int j = lane;
    const int i = j >> 1;

    const float a  = aux[row * 32 + 2 * i];
    const float bb = aux[row * 32 + 2 * i + 1];
    const float z0 = z[row * 32 + 2 * i];
    const float z1 = z[row * 32 + 2 * i + 1];

    const float f = expf(a * KDT);
    const float c = cosf(bb * KDT);
    const float s = sinf(bb * KDT);

    const float az = (j & 1) ? f * (s * z0 + c * z1)
                             : f * (c * z0 - s * z1);
    const float zj = (j & 1) ? z1 : z0;

    const float* bm = Bmat + (size_t)row * 512 + j * 16;
    const float* ur = u + (size_t)row * 16;
    float bu = 0.0f;
#pragma unroll
    for (int k = 0; k < 16; k++) bu = fmaf(bm[k], ur[k], bu);

    z_next[row * 32 + j] = tfround(zj + KDT * (az + bu));
}

// ---------------------------------------------------------------------------
static constexpr int smem_bytes(int BN) {
    return 4 * (128 * 20 + 16 * (BN + 8)) * 4;   // S=4, BK=16
}

extern "C" void kernel_launch(void* const* d_in, const int* in_sizes, int n_in,
                              void* d_out, int out_size)
{
    const float* x    = (const float*)d_in[0];
    const float* u    = (const float*)d_in[1];
    const float* e_w1 = (const float*)d_in[2];
    const float* e_b1 = (const float*)d_in[3];
    const float* e_w2 = (const float*)d_in[4];
    const float* e_b2 = (const float*)d_in[5];
    const float* e_w3 = (const float*)d_in[6];
    const float* e_b3 = (const float*)d_in[7];
    const float* d_w1 = (const float*)d_in[8];
    const float* d_b1 = (const float*)d_in[9];
    const float* d_w2 = (const float*)d_in[10];
    const float* d_b2 = (const float*)d_in[11];
    const float* d_w3 = (const float*)d_in[12];
    const float* d_b3 = (const float*)d_in[13];
    const float* d_w4 = (const float*)d_in[14];
    const float* d_b4 = (const float*)d_in[15];
    const float* a_w1 = (const float*)d_in[16];
    const float* a_b1 = (const float*)d_in[17];
    const float* a_w2 = (const float*)d_in[18];
    const float* a_b2 = (const float*)d_in[19];
    const float* a_w3 = (const float*)d_in[20];
    const float* a_b3 = (const float*)d_in[21];
    const float* b_w1 = (const float*)d_in[22];
    const float* b_b1 = (const float*)d_in[23];
    const float* b_w2 = (const float*)d_in[24];
    const float* b_b2 = (const float*)d_in[25];
    const float* b_w3 = (const float*)d_in[26];
    const float* b_b3 = (const float*)d_in[27];
    float* out = (float*)d_out;

    float *bufA, *bufB, *s1, *s2, *zb, *auxb, *Bm, *zn, *xr, *wr;
    cudaGetSymbolAddress((void**)&bufA, g_bufA);
    cudaGetSymbolAddress((void**)&bufB, g_bufB);
    cudaGetSymbolAddress((void**)&s1,   g_s1);
    cudaGetSymbolAddress((void**)&s2,   g_s2);
    cudaGetSymbolAddress((void**)&zb,   g_z);
    cudaGetSymbolAddress((void**)&auxb, g_aux);
    cudaGetSymbolAddress((void**)&Bm,   g_Bmat);
    cudaGetSymbolAddress((void**)&zn,   g_znext);
    cudaGetSymbolAddress((void**)&xr,   g_xr);
    cudaGetSymbolAddress((void**)&wr,   g_wr);

    // tf32-rounded weight copies (offsets in floats into g_wr)
    float* e_w1r = wr + 0;
    float* e_w2r = wr + 65536;
    float* e_w3r = wr + 1114112;
    float* d_w1r = wr + 1146880;
    float* d_w2r = wr + 1179648;
    float* d_w3r = wr + 2228224;
    float* d_w4r = wr + 3276800;
    float* a_w1r = wr + 3342336;
    float* a_w2r = wr + 3358720;
    float* a_w3r = wr + 3424256;
    float* b_w1r = wr + 3432448;
    float* b_w2r = wr + 3448832;
    float* b_w3r = wr + 3514368;

    // ---- one fused pre-round launch ----
    {
        SegPack p;
        auto set = [&](int i, const float* s, float* d, int n) {
            p.s[i].src = (const float4*)s;
            p.s[i].dst = (float4*)d;
            p.s[i].n4  = n / 4;
        };
        set(0,  x,    xr,    BATCH * 64);
        set(1,  e_w1, e_w1r, 64 * 1024);
        set(2,  e_w2, e_w2r, 1024 * 1024);
        set(3,  e_w3, e_w3r, 1024 * 32);
        set(4,  d_w1, d_w1r, 32 * 1024);
        set(5,  d_w2, d_w2r, 1024 * 1024);
        set(6,  d_w3, d_w3r, 1024 * 1024);
        set(7,  d_w4, d_w4r, 1024 * 64);
        set(8,  a_w1, a_w1r, 64 * 256);
        set(9,  a_w2, a_w2r, 256 * 256);
        set(10, a_w3, a_w3r, 256 * 32);
        set(11, b_w1, b_w1r, 64 * 256);
        set(12, b_w2, b_w2r, 256 * 256);
        set(13, b_w3, b_w3r, 256 * 512);
        round_all<<<dim3(64, NSEG), 256>>>(p);
    }

    const int B  = BATCH;
    const int GY = B / 128;
    const dim3 blk(256);

    constexpr int SM_BIG   = smem_bytes(128);   // 75,776 B -> 2 CTAs/SM
    constexpr int SM_MID   = smem_bytes(64);    // 59,392 B
    constexpr int SM_SMALL = smem_bytes(32);    // 51,200 B

    auto big_t   = gemm_tf32<128, 64, 32, true >;
    auto big_f   = gemm_tf32<128, 64, 32, false>;
    auto mid_f   = gemm_tf32< 64, 32, 32, false>;
    auto small_f = gemm_tf32< 32, 16, 32, false>;

    cudaFuncSetAttribute(big_t,   cudaFuncAttributeMaxDynamicSharedMemorySize, SM_BIG);
    cudaFuncSetAttribute(big_f,   cudaFuncAttributeMaxDynamicSharedMemorySize, SM_BIG);
    cudaFuncSetAttribute(mid_f,   cudaFuncAttributeMaxDynamicSharedMemorySize, SM_MID);
    cudaFuncSetAttribute(small_f, cudaFuncAttributeMaxDynamicSharedMemorySize, SM_SMALL);

    // ---- encoder: x -> h1 -> h2 -> z ----
    big_t  <<<dim3(8, GY), blk, SM_BIG  >>>(xr,   e_w1r, e_b1, bufA, B, 1024,   64);
    big_t  <<<dim3(8, GY), blk, SM_BIG  >>>(bufA, e_w2r, e_b2, bufB, B, 1024, 1024);
    small_f<<<dim3(1, GY), blk, SM_SMALL>>>(bufB, e_w3r, e_b3, zb,   B,   32, 1024);

    // ---- aux net ----
    big_t  <<<dim3(2, GY), blk, SM_BIG  >>>(xr, a_w1r, a_b1, s1,   B, 256,  64);
    big_t  <<<dim3(2, GY), blk, SM_BIG  >>>(s1, a_w2r, a_b2, s2,   B, 256, 256);
    small_f<<<dim3(1, GY), blk, SM_SMALL>>>(s2, a_w3r, a_b3, auxb, B,  32, 256);

    // ---- B net ----
    big_t  <<<dim3(2, GY), blk, SM_BIG  >>>(xr, b_w1r, b_b1, s1, B, 256,  64);
    big_t  <<<dim3(2, GY), blk, SM_BIG  >>>(s1, b_w2r, b_b2, s2, B, 256, 256);
    big_f  <<<dim3(4, GY), blk, SM_BIG  >>>(s2, b_w3r, b_b3, Bm, B, 512, 256);

    // ---- dynamics combine (rounds z_next for decoder) ----
    combine_kernel<<<B / 8, 256>>>(zb, auxb, Bm, u, zn);

    // ---- decoder ----
    big_t  <<<dim3(8, GY), blk, SM_BIG  >>>(zn,   d_w1r, d_b1, bufA, B, 1024,   32);
    big_t  <<<dim3(8, GY), blk, SM_BIG  >>>(bufA, d_w2r, d_b2, bufB, B, 1024, 1024);
    big_t  <<<dim3(8, GY), blk, SM_BIG  >>>(bufB, d_w3r, d_b3, bufA, B, 1024, 1024);
    mid_f  <<<dim3(1, GY), blk, SM_MID  >>>(bufA, d_w4r, d_b4, out,  B,   64, 1024);
}

// round 14
// speedup vs baseline: 4.8827x; 1.5930x over previous
#include <cuda_runtime.h>
#include <cuda_fp16.h>
#include <math.h>
#include <stdint.h>

// ---------------------------------------------------------------------------
// BlockKoopmanNet — fp16 tensor-core GEMMs (mma.sync.m16n8k16.f16, fp32
// accumulate), cp.async 4-stage pipeline. Weights pre-transposed+converted to
// half [N,K] in one prep pass; activations flow as half between layers.
// fp16 mantissa (10 bits) == tf32 mantissa, so accuracy matches the tf32
// build (1.07e-4) while doubling K per MMA and halving smem/DRAM traffic.
// B=16384, X=64, U=16, Z=32, H=1024, A=256. No tcgen05: harness assembles
// for plain sm_103 (R13 evidence), which lacks the arch-specific ISA.
// ---------------------------------------------------------------------------

#define KDT 0.02f
#define BATCH 16384

// Scratch (allocation-free rule: __device__ globals).
__device__ __half g_bufA[BATCH * 1024];
__device__ __half g_bufB[BATCH * 1024];
__device__ __half g_s1[BATCH * 256];
__device__ __half g_s2[BATCH * 256];
__device__ float  g_z[BATCH * 32];
__device__ float  g_aux[BATCH * 32];
__device__ float  g_Bmat[BATCH * 512];
__device__ __half g_znext[BATCH * 32];
__device__ __half g_xh[BATCH * 64];         // half-converted x
__device__ __half g_wh[3645440];            // half, transposed [N,K] weights

__device__ __forceinline__ void mma16(float* d, const uint32_t* a, const uint32_t* b) {
    asm volatile(
        "mma.sync.aligned.m16n8k16.row.col.f32.f16.f16.f32 "
        "{%0,%1,%2,%3}, {%4,%5,%6,%7}, {%8,%9}, {%0,%1,%2,%3};"
        : "+f"(d[0]), "+f"(d[1]), "+f"(d[2]), "+f"(d[3])
        : "r"(a[0]), "r"(a[1]), "r"(a[2]), "r"(a[3]), "r"(b[0]), "r"(b[1]));
}

__device__ __forceinline__ void cpa16(uint32_t dst, const void* src) {
    asm volatile("cp.async.cg.shared.global [%0], [%1], 16;" :: "r"(dst), "l"(src));
}
__device__ __forceinline__ void cpa_commit() {
    asm volatile("cp.async.commit_group;" ::: "memory");
}
__device__ __forceinline__ void cpa_wait2() {
    asm volatile("cp.async.wait_group 2;" ::: "memory");
}

// ---------------------------------------------------------------------------
// Prep 1: convert x to half.
// ---------------------------------------------------------------------------
__global__ void convert_x(const float4* __restrict__ src,
                          __half2* __restrict__ dst, int n4)
{
    int i = blockIdx.x * blockDim.x + threadIdx.x;
    const int stride = gridDim.x * blockDim.x;
    for (; i < n4; i += stride) {
        float4 v = src[i];
        dst[i * 2 + 0] = __floats2half2_rn(v.x, v.y);
        dst[i * 2 + 1] = __floats2half2_rn(v.z, v.w);
    }
}

// ---------------------------------------------------------------------------
// Prep 2: transpose + convert — WT[n][k] = half(W[k][n]) for ALL 13 weights.
// 32x32 smem tiles; every K and N here is a multiple of 32.
// ---------------------------------------------------------------------------
#define NTSEG 13
struct TSeg { const float* src; __half* dst; int K; int N; };
struct TSegPack { TSeg s[NTSEG]; };

__global__ void transpose_half(TSegPack p)
{
    const TSeg sg = p.s[blockIdx.z];
    const int n0 = blockIdx.x * 32, k0 = blockIdx.y * 32;
    if (n0 >= sg.N || k0 >= sg.K) return;
    __shared__ float tile[32][33];
    const int x = threadIdx.x, y = threadIdx.y;
#pragma unroll
    for (int i = 0; i < 4; i++)
        tile[y + i * 8][x] = sg.src[(size_t)(k0 + y + i * 8) * sg.N + n0 + x];
    __syncthreads();
#pragma unroll
    for (int i = 0; i < 4; i++)
        sg.dst[(size_t)(n0 + y + i * 8) * sg.K + k0 + x] =
            __float2half_rn(tile[x][y + i * 8]);
}

// ---------------------------------------------------------------------------
// C = act(A[M,K] @ WT[N,K]^T + bias). A half row-major, WT half [N,K].
// BM=128, BK=32 (2 x k16 MMA steps), 8 warps, S=4 cp.async pipeline with one
// __syncthreads per k-tile (wait_group 2; sync; issue(t+3); compute(t)).
// Both smem tiles use word-stride 20 (16 data words = 32 halves + 4 pad):
// fragment gather banks (20*g + tg) mod 32 are all distinct; rows 16B-aligned.
// OUTH: store half (feeds next GEMM); else float (feeds fp32 consumers).
// ---------------------------------------------------------------------------
template <int BN, int WM, int WN, bool ACT, bool OUTH>
__global__ void __launch_bounds__(256, 2)
gemm_fp16(const __half* __restrict__ A, const __half* __restrict__ WT,
          const float* __restrict__ bias, void* __restrict__ Cv,
          int M, int N, int K)
{
    constexpr int BM = 128, BK = 32, S = 4;
    constexpr int MT = WM / 16;
    constexpr int NT = WN / 8;
    constexpr int WARPS_N = BN / WN;
    constexpr int WARPS_M = 8 / WARPS_N;
    static_assert(WARPS_M * WM == BM, "warp grid must tile BM exactly");
    static_assert(WARPS_N * WN == BN, "warp grid must tile BN exactly");
    constexpr int STR = 20;                       // words per row (A and WT)
    constexpr int AWORDS = BM * STR;
    constexpr int WWORDS = BN * STR;
    constexpr int AV = (BM * 4) / 256;            // 16B chunks per thread (A)
    constexpr int WTOT = BN * 4;                  // 16B chunks in W tile
    constexpr int WV = (WTOT + 255) / 256;
    constexpr bool WGUARD = (WTOT % 256) != 0;

    extern __shared__ uint32_t smem_dyn[];
    uint32_t* Asm = smem_dyn;
    uint32_t* Wsm = smem_dyn + S * AWORDS;

    const int tid  = threadIdx.x;
    const int lane = tid & 31;
    const int wid  = tid >> 5;
    const int wm   = wid / WARPS_N;
    const int wn   = wid % WARPS_N;
    const int brow = blockIdx.y * BM;
    const int bcol = blockIdx.x * BN;
    const int g    = lane >> 2;
    const int tg   = lane & 3;

    const uint32_t a_sm = (uint32_t)__cvta_generic_to_shared(Asm);
    const uint32_t w_sm = (uint32_t)__cvta_generic_to_shared(Wsm);
    const int nk = K / BK;

    float acc[MT][NT][4];
#pragma unroll
    for (int m = 0; m < MT; m++)
#pragma unroll
        for (int n = 0; n < NT; n++)
#pragma unroll
            for (int q = 0; q < 4; q++) acc[m][n][q] = 0.0f;

    auto issue_tile = [&](int t) {
        if (t < nk) {
            const int s  = t % S;
            const int k0 = t * BK;
            const uint32_t ab = a_sm + (uint32_t)s * AWORDS * 4;
            const uint32_t wb = w_sm + (uint32_t)s * WWORDS * 4;
#pragma unroll
            for (int v = 0; v < AV; v++) {
                int idx = tid + v * 256;
                int row = idx >> 2, ch = idx & 3;   // 4 x 16B chunks per row
                cpa16(ab + (uint32_t)(row * STR + ch * 4) * 4,
                      A + (size_t)(brow + row) * K + k0 + ch * 8);
            }
#pragma unroll
            for (int v = 0; v < WV; v++) {
                int idx = tid + v * 256;
                if (!WGUARD || idx < WTOT) {
                    int row = idx >> 2, ch = idx & 3;
                    cpa16(wb + (uint32_t)(row * STR + ch * 4) * 4,
                          WT + (size_t)(bcol + row) * K + k0 + ch * 8);
                }
            }
        }
        cpa_commit();
    };

    issue_tile(0);
    issue_tile(1);
    issue_tile(2);

    for (int t = 0; t < nk; t++) {
        const int s = t % S;
        cpa_wait2();
        __syncthreads();
        issue_tile(t + 3);

        const uint32_t* As = Asm + s * AWORDS;
        const uint32_t* Ws = Wsm + s * WWORDS;

#pragma unroll
        for (int ks = 0; ks < 2; ks++) {            // 2 x k16 per tile
            uint32_t af[MT][4];
#pragma unroll
            for (int m = 0; m < MT; m++) {
                const int r0  = wm * WM + m * 16;
                const int col = ks * 8 + tg;
                af[m][0] = As[(r0 + g)     * STR + col];
                af[m][1] = As[(r0 + 8 + g) * STR + col];
                af[m][2] = As[(r0 + g)     * STR + col + 4];
                af[m][3] = As[(r0 + 8 + g) * STR + col + 4];
            }
            uint32_t bf[NT][2];
#pragma unroll
            for (int n = 0; n < NT; n++) {
                const int cb = wn * WN + n * 8 + g;
                bf[n][0] = Ws[cb * STR + ks * 8 + tg];
                bf[n][1] = Ws[cb * STR + ks * 8 + tg + 4];
            }
#pragma unroll
            for (int m = 0; m < MT; m++)
#pragma unroll
                for (int n = 0; n < NT; n++)
                    mma16(acc[m][n], af[m], bf[n]);
        }
    }

    // ---- epilogue: bias (+ SiLU); store half or float ----
#pragma unroll
    for (int m = 0; m < MT; m++) {
#pragma unroll
        for (int n = 0; n < NT; n++) {
            const int r0 = brow + wm * WM + m * 16 + g;
            const int cc = bcol + wn * WN + n * 8 + tg * 2;
            const float b0 = bias[cc], b1 = bias[cc + 1];
            float v0 = acc[m][n][0] + b0;
            float v1 = acc[m][n][1] + b1;
            float v2 = acc[m][n][2] + b0;
            float v3 = acc[m][n][3] + b1;
            if (ACT) {
                v0 = v0 / (1.0f + __expf(-v0));
                v1 = v1 / (1.0f + __expf(-v1));
                v2 = v2 / (1.0f + __expf(-v2));
                v3 = v3 / (1.0f + __expf(-v3));
            }
            if (OUTH) {
                __half* C = (__half*)Cv;
                *reinterpret_cast<__half2*>(C + (size_t)r0 * N + cc) =
                    __floats2half2_rn(v0, v1);
                *reinterpret_cast<__half2*>(C + (size_t)(r0 + 8) * N + cc) =
                    __floats2half2_rn(v2, v3);
            } else {
                float* C = (float*)Cv;
                float2 lo = {v0, v1}, hi = {v2, v3};
                *reinterpret_cast<float2*>(C + (size_t)r0 * N + cc) = lo;
                *reinterpret_cast<float2*>(C + (size_t)(r0 + 8) * N + cc) = hi;
            }
        }
    }
}

// ---------------------------------------------------------------------------
// Combine: z_next = half(z + DT*(Az + Bu)) — feeds the decoder GEMM.
// ---------------------------------------------------------------------------
__global__ void combine_kernel(const float* __restrict__ z,
                               const float* __restrict__ aux,
                               const float* __restrict__ Bmat,
                               const float* __restrict__ u,
                               __half* __restrict__ z_next)
{
    const int row  = blockIdx.x * (blockDim.x >> 5) + (threadIdx.x >> 5);
    const int lane = threadIdx.x & 31;
    if (row >= BATCH) return;

    const int j = lane;
    const int i = j >> 1;

    const float a  = aux[row * 32 + 2 * i];
    const float bb = aux[row * 32 + 2 * i + 1];
    const float z0 = z[row * 32 + 2 * i];
    const float z1 = z[row * 32 + 2 * i + 1];

    const float f = expf(a * KDT);
    const float c = cosf(bb * KDT);
    const float s = sinf(bb * KDT);

    const float az = (j & 1) ? f * (s * z0 + c * z1)
                             : f * (c * z0 - s * z1);
    const float zj = (j & 1) ? z1 : z0;

    const float* bm = Bmat + (size_t)row * 512 + j * 16;
    const float* ur = u + (size_t)row * 16;
    float bu = 0.0f;
#pragma unroll
    for (int k = 0; k < 16; k++) bu = fmaf(bm[k], ur[k], bu);

    z_next[row * 32 + j] = __float2half_rn(zj + KDT * (az + bu));
}

// ---------------------------------------------------------------------------
static constexpr int smem_fp16(int BN) {
    return 4 * (128 * 20 + BN * 20) * 4;   // S=4, stride 20 words
}

extern "C" void kernel_launch(void* const* d_in, const int* in_sizes, int n_in,
                              void* d_out, int out_size)
{
    const float* x    = (const float*)d_in[0];
    const float* u    = (const float*)d_in[1];
    const float* e_w1 = (const float*)d_in[2];
    const float* e_b1 = (const float*)d_in[3];
    const float* e_w2 = (const float*)d_in[4];
    const float* e_b2 = (const float*)d_in[5];
    const float* e_w3 = (const float*)d_in[6];
    const float* e_b3 = (const float*)d_in[7];
    const float* d_w1 = (const float*)d_in[8];
    const float* d_b1 = (const float*)d_in[9];
    const float* d_w2 = (const float*)d_in[10];
    const float* d_b2 = (const float*)d_in[11];
    const float* d_w3 = (const float*)d_in[12];
    const float* d_b3 = (const float*)d_in[13];
    const float* d_w4 = (const float*)d_in[14];
    const float* d_b4 = (const float*)d_in[15];
    const float* a_w1 = (const float*)d_in[16];
    const float* a_b1 = (const float*)d_in[17];
    const float* a_w2 = (const float*)d_in[18];
    const float* a_b2 = (const float*)d_in[19];
    const float* a_w3 = (const float*)d_in[20];
    const float* a_b3 = (const float*)d_in[21];
    const float* b_w1 = (const float*)d_in[22];
    const float* b_b1 = (const float*)d_in[23];
    const float* b_w2 = (const float*)d_in[24];
    const float* b_b2 = (const float*)d_in[25];
    const float* b_w3 = (const float*)d_in[26];
    const float* b_b3 = (const float*)d_in[27];
    float* out = (float*)d_out;

    __half *bufA, *bufB, *s1, *s2, *zn, *xh, *wh;
    float  *zb, *auxb, *Bm;
    cudaGetSymbolAddress((void**)&bufA, g_bufA);
    cudaGetSymbolAddress((void**)&bufB, g_bufB);
    cudaGetSymbolAddress((void**)&s1,   g_s1);
    cudaGetSymbolAddress((void**)&s2,   g_s2);
    cudaGetSymbolAddress((void**)&zb,   g_z);
    cudaGetSymbolAddress((void**)&auxb, g_aux);
    cudaGetSymbolAddress((void**)&Bm,   g_Bmat);
    cudaGetSymbolAddress((void**)&zn,   g_znext);
    cudaGetSymbolAddress((void**)&xh,   g_xh);
    cudaGetSymbolAddress((void**)&wh,   g_wh);

    // Transposed half weights in g_wh (offsets in halves).
    __half* e_w1t = wh + 0;          // [1024][64]
    __half* e_w2t = wh + 65536;      // [1024][1024]
    __half* e_w3t = wh + 1114112;    // [32][1024]
    __half* d_w1t = wh + 1146880;    // [1024][32]
    __half* d_w2t = wh + 1179648;    // [1024][1024]
    __half* d_w3t = wh + 2228224;    // [1024][1024]
    __half* d_w4t = wh + 3276800;    // [64][1024]
    __half* a_w1t = wh + 3342336;    // [256][64]
    __half* a_w2t = wh + 3358720;    // [256][256]
    __half* a_w3t = wh + 3424256;    // [32][256]
    __half* b_w1t = wh + 3432448;    // [256][64]
    __half* b_w2t = wh + 3448832;    // [256][256]
    __half* b_w3t = wh + 3514368;    // [512][256]

    // ---- prep: convert x + transpose/convert all weights (2 launches) ----
    convert_x<<<256, 256>>>((const float4*)x, (__half2*)xh, BATCH * 64 / 4);
    {
        TSegPack p;
        auto set = [&](int i, const float* s, __half* d, int K, int N) {
            p.s[i].src = s; p.s[i].dst = d; p.s[i].K = K; p.s[i].N = N;
        };
        set(0,  e_w1, e_w1t,   64, 1024);
        set(1,  e_w2, e_w2t, 1024, 1024);
        set(2,  e_w3, e_w3t, 1024,   32);
        set(3,  d_w1, d_w1t,   32, 1024);
        set(4,  d_w2, d_w2t, 1024, 1024);
        set(5,  d_w3, d_w3t, 1024, 1024);
        set(6,  d_w4, d_w4t, 1024,   64);
        set(7,  a_w1, a_w1t,   64,  256);
        set(8,  a_w2, a_w2t,  256,  256);
        set(9,  a_w3, a_w3t,  256,   32);
        set(10, b_w1, b_w1t,   64,  256);
        set(11, b_w2, b_w2t,  256,  256);
        set(12, b_w3, b_w3t,  256,  512);
        transpose_half<<<dim3(32, 32, NTSEG), dim3(32, 8)>>>(p);
    }

    const int B  = BATCH;
    const int GY = B / 128;
    const dim3 blk(256);

    constexpr int SM_BIG   = smem_fp16(128);   // 81,920 B
    constexpr int SM_MID   = smem_fp16(64);    // 61,440 B
    constexpr int SM_SMALL = smem_fp16(32);    // 51,200 B

    auto big_t   = gemm_fp16<128, 64, 32, true,  true >;   // ACT -> half out
    auto big_f   = gemm_fp16<128, 64, 32, false, false>;   // b_w3 -> float
    auto mid_f   = gemm_fp16< 64, 32, 32, false, false>;   // d_w4 -> float
    auto small_f = gemm_fp16< 32, 16, 32, false, false>;   // e_w3/a_w3 -> float

    cudaFuncSetAttribute(big_t,   cudaFuncAttributeMaxDynamicSharedMemorySize, SM_BIG);
    cudaFuncSetAttribute(big_f,   cudaFuncAttributeMaxDynamicSharedMemorySize, SM_BIG);
    cudaFuncSetAttribute(mid_f,   cudaFuncAttributeMaxDynamicSharedMemorySize, SM_MID);
    cudaFuncSetAttribute(small_f, cudaFuncAttributeMaxDynamicSharedMemorySize, SM_SMALL);

    // ---- encoder: x -> h1 -> h2 -> z ----
    big_t  <<<dim3(8, GY), blk, SM_BIG  >>>(xh,   e_w1t, e_b1, bufA, B, 1024,   64);
    big_t  <<<dim3(8, GY), blk, SM_BIG  >>>(bufA, e_w2t, e_b2, bufB, B, 1024, 1024);
    small_f<<<dim3(1, GY), blk, SM_SMALL>>>(bufB, e_w3t, e_b3, zb,   B,   32, 1024);

    // ---- aux net ----
    big_t  <<<dim3(2, GY), blk, SM_BIG  >>>(xh, a_w1t, a_b1, s1,   B, 256,  64);
    big_t  <<<dim3(2, GY), blk, SM_BIG  >>>(s1, a_w2t, a_b2, s2,   B, 256, 256);
    small_f<<<dim3(1, GY), blk, SM_SMALL>>>(s2, a_w3t, a_b3, auxb, B,  32, 256);

    // ---- B net ----
    big_t  <<<dim3(2, GY), blk, SM_BIG  >>>(xh, b_w1t, b_b1, s1, B, 256,  64);
    big_t  <<<dim3(2, GY), blk, SM_BIG  >>>(s1, b_w2t, b_b2, s2, B, 256, 256);
    big_f  <<<dim3(4, GY), blk, SM_BIG  >>>(s2, b_w3t, b_b3, Bm, B, 512, 256);

    // ---- dynamics combine (half z_next for decoder) ----
    combine_kernel<<<B / 8, 256>>>(zb, auxb, Bm, u, zn);

    // ---- decoder ----
    big_t  <<<dim3(8, GY), blk, SM_BIG  >>>(zn,   d_w1t, d_b1, bufA, B, 1024,   32);
    big_t  <<<dim3(8, GY), blk, SM_BIG  >>>(bufA, d_w2t, d_b2, bufB, B, 1024, 1024);
    big_t  <<<dim3(8, GY), blk, SM_BIG  >>>(bufB, d_w3t, d_b3, bufA, B, 1024, 1024);
    mid_f  <<<dim3(1, GY), blk, SM_MID  >>>(bufA, d_w4t, d_b4, out,  B,   64, 1024);
}

// round 15
// speedup vs baseline: 5.3229x; 1.0901x over previous
#include <cuda_runtime.h>
#include <cuda_fp16.h>
#include <math.h>
#include <stdint.h>

// ---------------------------------------------------------------------------
// BlockKoopmanNet — fp16 tensor-core GEMMs (mma.sync.m16n8k16.f16, fp32
// accumulate) with ldmatrix fragment loads, cp.async 4-stage pipeline.
// Weights pre-transposed+converted to half [N,K]; activations flow as half.
// B=16384, X=64, U=16, Z=32, H=1024, A=256.
// ---------------------------------------------------------------------------

#define KDT 0.02f
#define BATCH 16384

// Scratch (allocation-free rule: __device__ globals).
__device__ __half g_bufA[BATCH * 1024];
__device__ __half g_bufB[BATCH * 1024];
__device__ __half g_s1[BATCH * 256];
__device__ __half g_s2[BATCH * 256];
__device__ float  g_z[BATCH * 32];
__device__ float  g_aux[BATCH * 32];
__device__ float  g_Bmat[BATCH * 512];
__device__ __half g_znext[BATCH * 32];
__device__ __half g_xh[BATCH * 64];         // half-converted x
__device__ __half g_wh[3645440];            // half, transposed [N,K] weights

__device__ __forceinline__ void mma16(float* d, const uint32_t* a, const uint32_t* b) {
    asm volatile(
        "mma.sync.aligned.m16n8k16.row.col.f32.f16.f16.f32 "
        "{%0,%1,%2,%3}, {%4,%5,%6,%7}, {%8,%9}, {%0,%1,%2,%3};"
        : "+f"(d[0]), "+f"(d[1]), "+f"(d[2]), "+f"(d[3])
        : "r"(a[0]), "r"(a[1]), "r"(a[2]), "r"(a[3]), "r"(b[0]), "r"(b[1]));
}

__device__ __forceinline__ void ldsm4(uint32_t& r0, uint32_t& r1,
                                      uint32_t& r2, uint32_t& r3, uint32_t addr) {
    asm volatile("ldmatrix.sync.aligned.m8n8.x4.shared.b16 {%0,%1,%2,%3}, [%4];"
                 : "=r"(r0), "=r"(r1), "=r"(r2), "=r"(r3) : "r"(addr));
}

__device__ __forceinline__ void cpa16(uint32_t dst, const void* src) {
    asm volatile("cp.async.cg.shared.global [%0], [%1], 16;" :: "r"(dst), "l"(src));
}
__device__ __forceinline__ void cpa_commit() {
    asm volatile("cp.async.commit_group;" ::: "memory");
}
__device__ __forceinline__ void cpa_wait2() {
    asm volatile("cp.async.wait_group 2;" ::: "memory");
}

// ---------------------------------------------------------------------------
// Prep 1: convert x to half.
// ---------------------------------------------------------------------------
__global__ void convert_x(const float4* __restrict__ src,
                          __half2* __restrict__ dst, int n4)
{
    int i = blockIdx.x * blockDim.x + threadIdx.x;
    const int stride = gridDim.x * blockDim.x;
    for (; i < n4; i += stride) {
        float4 v = src[i];
        dst[i * 2 + 0] = __floats2half2_rn(v.x, v.y);
        dst[i * 2 + 1] = __floats2half2_rn(v.z, v.w);
    }
}

// ---------------------------------------------------------------------------
// Prep 2: transpose + convert — WT[n][k] = half(W[k][n]) for ALL 13 weights.
// ---------------------------------------------------------------------------
#define NTSEG 13
struct TSeg { const float* src; __half* dst; int K; int N; };
struct TSegPack { TSeg s[NTSEG]; };

__global__ void transpose_half(TSegPack p)
{
    const TSeg sg = p.s[blockIdx.z];
    const int n0 = blockIdx.x * 32, k0 = blockIdx.y * 32;
    if (n0 >= sg.N || k0 >= sg.K) return;
    __shared__ float tile[32][33];
    const int x = threadIdx.x, y = threadIdx.y;
#pragma unroll
    for (int i = 0; i < 4; i++)
        tile[y + i * 8][x] = sg.src[(size_t)(k0 + y + i * 8) * sg.N + n0 + x];
    __syncthreads();
#pragma unroll
    for (int i = 0; i < 4; i++)
        sg.dst[(size_t)(n0 + y + i * 8) * sg.K + k0 + x] =
            __float2half_rn(tile[x][y + i * 8]);
}

// ---------------------------------------------------------------------------
// C = act(A[M,K] @ WT[N,K]^T + bias). A half row-major, WT half [N,K].
// BM=128, BK=32 (2 x k16 MMA steps), 8 warps, S=4 cp.async pipeline, one
// __syncthreads per k-tile. Fragment loads via ldmatrix.m8n8.x4 (4 for A,
// 2 for B per warp per k-step; word-stride-20 rows make every ldmatrix
// phase hit all 32 banks exactly once).
// OUTH: store half (feeds next GEMM); else float.
// ---------------------------------------------------------------------------
template <int BN, int WM, int WN, bool ACT, bool OUTH>
__global__ void __launch_bounds__(256, 2)
gemm_fp16(const __half* __restrict__ A, const __half* __restrict__ WT,
          const float* __restrict__ bias, void* __restrict__ Cv,
          int M, int N, int K)
{
    constexpr int BM = 128, BK = 32, S = 4;
    constexpr int MT = WM / 16;
    constexpr int NT = WN / 8;
    static_assert(NT % 2 == 0, "B ldmatrix.x4 covers n-tile pairs");
    constexpr int WARPS_N = BN / WN;
    constexpr int WARPS_M = 8 / WARPS_N;
    static_assert(WARPS_M * WM == BM, "warp grid must tile BM exactly");
    static_assert(WARPS_N * WN == BN, "warp grid must tile BN exactly");
    constexpr int STR = 20;                       // words per row (A and WT)
    constexpr int AWORDS = BM * STR;
    constexpr int WWORDS = BN * STR;
    constexpr int AV = (BM * 4) / 256;            // 16B chunks per thread (A)
    constexpr int WTOT = BN * 4;                  // 16B chunks in W tile
    constexpr int WV = (WTOT + 255) / 256;
    constexpr bool WGUARD = (WTOT % 256) != 0;

    extern __shared__ uint32_t smem_dyn[];
    uint32_t* Asm = smem_dyn;
    uint32_t* Wsm = smem_dyn + S * AWORDS;

    const int tid  = threadIdx.x;
    const int lane = tid & 31;
    const int wid  = tid >> 5;
    const int wm   = wid / WARPS_N;
    const int wn   = wid % WARPS_N;
    const int brow = blockIdx.y * BM;
    const int bcol = blockIdx.x * BN;
    const int g    = lane >> 2;
    const int tg   = lane & 3;

    // ldmatrix lane roles (quadrant q = lane/8, r = lane%8):
    //   A x4:  q0:(row +r,   word +0)  q1:(row +8+r, word +0)
    //          q2:(row +r,   word +4)  q3:(row +8+r, word +4)
    //   B x4:  q0:(n-tile lo +r, +0)   q1:(lo +r, +4)
    //          q2:(n-tile hi +r, +0)   q3:(hi +r, +4)
    const int q  = lane >> 3;
    const int rr = lane & 7;
    const int a_row = ((q & 1) << 3) + rr;        // 0..15
    const int a_col = (q >> 1) << 2;              // 0 or 4 words
    const int b_row = ((q >> 1) << 3) + rr;       // 0..15 (two n8 tiles)
    const int b_col = (q & 1) << 2;               // 0 or 4 words

    const uint32_t a_sm = (uint32_t)__cvta_generic_to_shared(Asm);
    const uint32_t w_sm = (uint32_t)__cvta_generic_to_shared(Wsm);
    const int nk = K / BK;

    float acc[MT][NT][4];
#pragma unroll
    for (int m = 0; m < MT; m++)
#pragma unroll
        for (int n = 0; n < NT; n++)
#pragma unroll
            for (int qq = 0; qq < 4; qq++) acc[m][n][qq] = 0.0f;

    auto issue_tile = [&](int t) {
        if (t < nk) {
            const int s  = t % S;
            const int k0 = t * BK;
            const uint32_t ab = a_sm + (uint32_t)s * AWORDS * 4;
            const uint32_t wb = w_sm + (uint32_t)s * WWORDS * 4;
#pragma unroll
            for (int v = 0; v < AV; v++) {
                int idx = tid + v * 256;
                int row = idx >> 2, ch = idx & 3;   // 4 x 16B chunks per row
                cpa16(ab + (uint32_t)(row * STR + ch * 4) * 4,
                      A + (size_t)(brow + row) * K + k0 + ch * 8);
            }
#pragma unroll
            for (int v = 0; v < WV; v++) {
                int idx = tid + v * 256;
                if (!WGUARD || idx < WTOT) {
                    int row = idx >> 2, ch = idx & 3;
                    cpa16(wb + (uint32_t)(row * STR + ch * 4) * 4,
                          WT + (size_t)(bcol + row) * K + k0 + ch * 8);
                }
            }
        }
        cpa_commit();
    };

    issue_tile(0);
    issue_tile(1);
    issue_tile(2);

    for (int t = 0; t < nk; t++) {
        const int s = t % S;
        cpa_wait2();
        __syncthreads();
        issue_tile(t + 3);

        const uint32_t a_st = a_sm + (uint32_t)s * AWORDS * 4;
        const uint32_t w_st = w_sm + (uint32_t)s * WWORDS * 4;

#pragma unroll
        for (int ks = 0; ks < 2; ks++) {            // 2 x k16 per tile
            uint32_t af[MT][4];
#pragma unroll
            for (int m = 0; m < MT; m++) {
                const int r0 = wm * WM + m * 16;
                ldsm4(af[m][0], af[m][1], af[m][2], af[m][3],
                      a_st + (uint32_t)((r0 + a_row) * STR + ks * 8 + a_col) * 4);
            }
            uint32_t bf[NT][2];
#pragma unroll
            for (int p = 0; p < NT / 2; p++) {
                const int cb0 = wn * WN + p * 16;
                ldsm4(bf[2 * p][0], bf[2 * p][1], bf[2 * p + 1][0], bf[2 * p + 1][1],
                      w_st + (uint32_t)((cb0 + b_row) * STR + ks * 8 + b_col) * 4);
            }
#pragma unroll
            for (int m = 0; m < MT; m++)
#pragma unroll
                for (int n = 0; n < NT; n++)
                    mma16(acc[m][n], af[m], bf[n]);
        }
    }

    // ---- epilogue: bias (+ SiLU); store half or float ----
#pragma unroll
    for (int m = 0; m < MT; m++) {
#pragma unroll
        for (int n = 0; n < NT; n++) {
            const int r0 = brow + wm * WM + m * 16 + g;
            const int cc = bcol + wn * WN + n * 8 + tg * 2;
            const float b0 = bias[cc], b1 = bias[cc + 1];
            float v0 = acc[m][n][0] + b0;
            float v1 = acc[m][n][1] + b1;
            float v2 = acc[m][n][2] + b0;
            float v3 = acc[m][n][3] + b1;
            if (ACT) {
                v0 = v0 / (1.0f + __expf(-v0));
                v1 = v1 / (1.0f + __expf(-v1));
                v2 = v2 / (1.0f + __expf(-v2));
                v3 = v3 / (1.0f + __expf(-v3));
            }
            if (OUTH) {
                __half* C = (__half*)Cv;
                *reinterpret_cast<__half2*>(C + (size_t)r0 * N + cc) =
                    __floats2half2_rn(v0, v1);
                *reinterpret_cast<__half2*>(C + (size_t)(r0 + 8) * N + cc) =
                    __floats2half2_rn(v2, v3);
            } else {
                float* C = (float*)Cv;
                float2 lo = {v0, v1}, hi = {v2, v3};
                *reinterpret_cast<float2*>(C + (size_t)r0 * N + cc) = lo;
                *reinterpret_cast<float2*>(C + (size_t)(r0 + 8) * N + cc) = hi;
            }
        }
    }
}

// ---------------------------------------------------------------------------
// Combine: z_next = half(z + DT*(Az + Bu)) — feeds the decoder GEMM.
// ---------------------------------------------------------------------------
__global__ void combine_kernel(const float* __restrict__ z,
                               const float* __restrict__ aux,
                               const float* __restrict__ Bmat,
                               const float* __restrict__ u,
                               __half* __restrict__ z_next)
{
    const int row  = blockIdx.x * (blockDim.x >> 5) + (threadIdx.x >> 5);
    const int lane = threadIdx.x & 31;
    if (row >= BATCH) return;

    const int j = lane;
    const int i = j >> 1;

    const float a  = aux[row * 32 + 2 * i];
    const float bb = aux[row * 32 + 2 * i + 1];
    const float z0 = z[row * 32 + 2 * i];
    const float z1 = z[row * 32 + 2 * i + 1];

    const float f = expf(a * KDT);
    const float c = cosf(bb * KDT);
    const float s = sinf(bb * KDT);

    const float az = (j & 1) ? f * (s * z0 + c * z1)
                             : f * (c * z0 - s * z1);
    const float zj = (j & 1) ? z1 : z0;

    const float* bm = Bmat + (size_t)row * 512 + j * 16;
    const float* ur = u + (size_t)row * 16;
    float bu = 0.0f;
#pragma unroll
    for (int k = 0; k < 16; k++) bu = fmaf(bm[k], ur[k], bu);

    z_next[row * 32 + j] = __float2half_rn(zj + KDT * (az + bu));
}

// ---------------------------------------------------------------------------
static constexpr int smem_fp16(int BN) {
    return 4 * (128 * 20 + BN * 20) * 4;   // S=4, stride 20 words
}

extern "C" void kernel_launch(void* const* d_in, const int* in_sizes, int n_in,
                              void* d_out, int out_size)
{
    const float* x    = (const float*)d_in[0];
    const float* u    = (const float*)d_in[1];
    const float* e_w1 = (const float*)d_in[2];
    const float* e_b1 = (const float*)d_in[3];
    const float* e_w2 = (const float*)d_in[4];
    const float* e_b2 = (const float*)d_in[5];
    const float* e_w3 = (const float*)d_in[6];
    const float* e_b3 = (const float*)d_in[7];
    const float* d_w1 = (const float*)d_in[8];
    const float* d_b1 = (const float*)d_in[9];
    const float* d_w2 = (const float*)d_in[10];
    const float* d_b2 = (const float*)d_in[11];
    const float* d_w3 = (const float*)d_in[12];
    const float* d_b3 = (const float*)d_in[13];
    const float* d_w4 = (const float*)d_in[14];
    const float* d_b4 = (const float*)d_in[15];
    const float* a_w1 = (const float*)d_in[16];
    const float* a_b1 = (const float*)d_in[17];
    const float* a_w2 = (const float*)d_in[18];
    const float* a_b2 = (const float*)d_in[19];
    const float* a_w3 = (const float*)d_in[20];
    const float* a_b3 = (const float*)d_in[21];
    const float* b_w1 = (const float*)d_in[22];
    const float* b_b1 = (const float*)d_in[23];
    const float* b_w2 = (const float*)d_in[24];
    const float* b_b2 = (const float*)d_in[25];
    const float* b_w3 = (const float*)d_in[26];
    const float* b_b3 = (const float*)d_in[27];
    float* out = (float*)d_out;

    __half *bufA, *bufB, *s1, *s2, *zn, *xh, *wh;
    float  *zb, *auxb, *Bm;
    cudaGetSymbolAddress((void**)&bufA, g_bufA);
    cudaGetSymbolAddress((void**)&bufB, g_bufB);
    cudaGetSymbolAddress((void**)&s1,   g_s1);
    cudaGetSymbolAddress((void**)&s2,   g_s2);
    cudaGetSymbolAddress((void**)&zb,   g_z);
    cudaGetSymbolAddress((void**)&auxb, g_aux);
    cudaGetSymbolAddress((void**)&Bm,   g_Bmat);
    cudaGetSymbolAddress((void**)&zn,   g_znext);
    cudaGetSymbolAddress((void**)&xh,   g_xh);
    cudaGetSymbolAddress((void**)&wh,   g_wh);

    // Transposed half weights in g_wh (offsets in halves).
    __half* e_w1t = wh + 0;          // [1024][64]
    __half* e_w2t = wh + 65536;      // [1024][1024]
    __half* e_w3t = wh + 1114112;    // [32][1024]
    __half* d_w1t = wh + 1146880;    // [1024][32]
    __half* d_w2t = wh + 1179648;    // [1024][1024]
    __half* d_w3t = wh + 2228224;    // [1024][1024]
    __half* d_w4t = wh + 3276800;    // [64][1024]
    __half* a_w1t = wh + 3342336;    // [256][64]
    __half* a_w2t = wh + 3358720;    // [256][256]
    __half* a_w3t = wh + 3424256;    // [32][256]
    __half* b_w1t = wh + 3432448;    // [256][64]
    __half* b_w2t = wh + 3448832;    // [256][256]
    __half* b_w3t = wh + 3514368;    // [512][256]

    // ---- prep: convert x + transpose/convert all weights (2 launches) ----
    convert_x<<<256, 256>>>((const float4*)x, (__half2*)xh, BATCH * 64 / 4);
    {
        TSegPack p;
        auto set = [&](int i, const float* s, __half* d, int K, int N) {
            p.s[i].src = s; p.s[i].dst = d; p.s[i].K = K; p.s[i].N = N;
        };
        set(0,  e_w1, e_w1t,   64, 1024);
        set(1,  e_w2, e_w2t, 1024, 1024);
        set(2,  e_w3, e_w3t, 1024,   32);
        set(3,  d_w1, d_w1t,   32, 1024);
        set(4,  d_w2, d_w2t, 1024, 1024);
        set(5,  d_w3, d_w3t, 1024, 1024);
        set(6,  d_w4, d_w4t, 1024,   64);
        set(7,  a_w1, a_w1t,   64,  256);
        set(8,  a_w2, a_w2t,  256,  256);
        set(9,  a_w3, a_w3t,  256,   32);
        set(10, b_w1, b_w1t,   64,  256);
        set(11, b_w2, b_w2t,  256,  256);
        set(12, b_w3, b_w3t,  256,  512);
        transpose_half<<<dim3(32, 32, NTSEG), dim3(32, 8)>>>(p);
    }

    const int B  = BATCH;
    const int GY = B / 128;
    const dim3 blk(256);

    constexpr int SM_BIG   = smem_fp16(128);   // 81,920 B
    constexpr int SM_MID   = smem_fp16(64);    // 61,440 B
    constexpr int SM_SMALL = smem_fp16(32);    // 51,200 B

    auto big_t   = gemm_fp16<128, 64, 32, true,  true >;   // ACT -> half out
    auto big_f   = gemm_fp16<128, 64, 32, false, false>;   // b_w3 -> float
    auto mid_f   = gemm_fp16< 64, 32, 32, false, false>;   // d_w4 -> float
    auto small_f = gemm_fp16< 32, 16, 32, false, false>;   // e_w3/a_w3 -> float

    cudaFuncSetAttribute(big_t,   cudaFuncAttributeMaxDynamicSharedMemorySize, SM_BIG);
    cudaFuncSetAttribute(big_f,   cudaFuncAttributeMaxDynamicSharedMemorySize, SM_BIG);
    cudaFuncSetAttribute(mid_f,   cudaFuncAttributeMaxDynamicSharedMemorySize, SM_MID);
    cudaFuncSetAttribute(small_f, cudaFuncAttributeMaxDynamicSharedMemorySize, SM_SMALL);

    // ---- encoder: x -> h1 -> h2 -> z ----
    big_t  <<<dim3(8, GY), blk, SM_BIG  >>>(xh,   e_w1t, e_b1, bufA, B, 1024,   64);
    big_t  <<<dim3(8, GY), blk, SM_BIG  >>>(bufA, e_w2t, e_b2, bufB, B, 1024, 1024);
    small_f<<<dim3(1, GY), blk, SM_SMALL>>>(bufB, e_w3t, e_b3, zb,   B,   32, 1024);

    // ---- aux net ----
    big_t  <<<dim3(2, GY), blk, SM_BIG  >>>(xh, a_w1t, a_b1, s1,   B, 256,  64);
    big_t  <<<dim3(2, GY), blk, SM_BIG  >>>(s1, a_w2t, a_b2, s2,   B, 256, 256);
    small_f<<<dim3(1, GY), blk, SM_SMALL>>>(s2, a_w3t, a_b3, auxb, B,  32, 256);

    // ---- B net ----
    big_t  <<<dim3(2, GY), blk, SM_BIG  >>>(xh, b_w1t, b_b1, s1, B, 256,  64);
    big_t  <<<dim3(2, GY), blk, SM_BIG  >>>(s1, b_w2t, b_b2, s2, B, 256, 256);
    big_f  <<<dim3(4, GY), blk, SM_BIG  >>>(s2, b_w3t, b_b3, Bm, B, 512, 256);

    // ---- dynamics combine (half z_next for decoder) ----
    combine_kernel<<<B / 8, 256>>>(zb, auxb, Bm, u, zn);

    // ---- decoder ----
    big_t  <<<dim3(8, GY), blk, SM_BIG  >>>(zn,   d_w1t, d_b1, bufA, B, 1024,   32);
    big_t  <<<dim3(8, GY), blk, SM_BIG  >>>(bufA, d_w2t, d_b2, bufB, B, 1024, 1024);
    big_t  <<<dim3(8, GY), blk, SM_BIG  >>>(bufB, d_w3t, d_b3, bufA, B, 1024, 1024);
    mid_f  <<<dim3(1, GY), blk, SM_MID  >>>(bufA, d_w4t, d_b4, out,  B,   64, 1024);
}